// round 11
// baseline (speedup 1.0000x reference)
#include <cuda_runtime.h>

#define B_     2
#define NPART  512
#define BN     1024
#define GBINS  48
#define TWO_PI 6.283185307179586f
#define INV_2PI 0.15915494309189535f

// ---------------- static device scratch ----------------
__device__ float    g_p1[BN * 2];
__device__ float    g_regC[BN * 128];
__device__ float    g_regD[BN * 128];
__device__ float4   g_ent[BN * 512];          // (wb(1-wr), wb*wr, wt, j|r0<<16)
__device__ int      g_binStart[BN * 17];      // CSR over 16 t-columns
__device__ float    g_F[BN * 49 * 128];       // 48 bins * CK + CK dense tail
__device__ float    g_out[BN * 128];
__device__ float    g_actA[BN * 128];
__device__ float    g_actB[BN * 128];
__device__ float    g_Wbig[1555456];          // conv+dense merged, 5 layers
__device__ float    g_part[28 * BN * 64];     // split-K partials (max 1.83M floats)
__device__ float    g_oc[BN * 24];
__device__ float    g_od[BN * 24];

// merged weight offsets: KDp*OKt = {6272*64, 3136*64, 3136*128, 6272*64, 3136*48}
__constant__ int c_wOff[6] = {0, 401408, 602112, 1003520, 1404928, 1555456};

// ---------------- f32x2 helpers ----------------
__device__ __forceinline__ unsigned long long pack2(float x) {
    unsigned long long r;
    asm("mov.b64 %0, {%1, %1};" : "=l"(r) : "f"(x));
    return r;
}
__device__ __forceinline__ unsigned long long ffma2(unsigned long long a,
                                                    unsigned long long b,
                                                    unsigned long long c) {
    unsigned long long d;
    asm("fma.rn.f32x2 %0, %1, %2, %3;" : "=l"(d) : "l"(a), "l"(b), "l"(c));
    return d;
}
union F4U { float4 f4; float f[4]; unsigned long long u2[2]; };
union F2U { float2 f2; unsigned long long u2; };

// ---------------- prep: geom+lift (blocks 0..BN-1) and expand (rest) ----------------
__global__ void __launch_bounds__(256) prep_kernel(
        const float* __restrict__ mask, const float* __restrict__ p0,
        const float* __restrict__ v0, const float* __restrict__ a,
        const float* __restrict__ p0_enc, const float* __restrict__ v0_enc,
        const float* __restrict__ lc, const float* __restrict__ ld,
        const float* __restrict__ Wc0, const float* __restrict__ Wc1,
        const float* __restrict__ Wc2, const float* __restrict__ Wc3,
        const float* __restrict__ Wc4,
        const float* __restrict__ Wd0, const float* __restrict__ Wd1,
        const float* __restrict__ Wd2, const float* __restrict__ Wd3,
        const float* __restrict__ Wd4) {
    int tid = threadIdx.x;
    if (blockIdx.x >= BN) {
        // ---- expand merged conv+dense weight matrix ----
        const int Cs[5]   = {16, 8, 8, 16, 8};
        const int OKc[5]  = {32, 64, 128, 64, 24};   // conv output cols
        const int OKt[5]  = {64, 64, 128, 64, 48};   // total cols (split layers add dense cols)
        int idx = (blockIdx.x - BN) * 256 + tid;
        if (idx >= 1555456) return;
        int l = 0;
        while (idx >= c_wOff[l + 1]) ++l;
        int loc = idx - c_wOff[l];
        const float* Wc = (l == 0) ? Wc0 : (l == 1) ? Wc1 : (l == 2) ? Wc2 : (l == 3) ? Wc3 : Wc4;
        const float* Wd = (l == 0) ? Wd0 : (l == 1) ? Wd1 : (l == 2) ? Wd2 : (l == 3) ? Wd3 : Wd4;
        int C = Cs[l], okc = OKc[l], okt = OKt[l];
        int KD = 384 * C;                            // GBINS*C*8
        int om2 = loc % okt;
        int kk = loc / okt;
        float val = 0.f;
        if (kk < KD) {
            if (om2 < okc) {
                int n = kk & 7, c = (kk >> 3) % C, g = (kk >> 3) / C;
                int r = g >> 4, t = g & 15, o = om2 >> 3, m = om2 & 7;
                val = Wc[(((o * C + c) * 8 + ((n - m) & 7)) * 3 + r) * 16 + ((t - 2 * m) & 15)];
            }
        } else {
            int cn = kk - KD;
            int om = (okt == okc) ? om2 : om2 - okc;
            if (om >= 0) {
                int o = om >> 3, m = om & 7, c = cn >> 3, n = cn & 7;
                val = Wd[(o * C + c) * 8 + ((m - n) & 7)];
            }
        }
        g_Wbig[idx] = val;
        return;
    }

    __shared__ float sx[NPART], sy[NPART], smk[NPART], sw[NPART];
    __shared__ float red[256];
    __shared__ int cnt[16], offs[16], bstart[17];
    int bi = blockIdx.x;
    int b = bi >> 9, i = bi & 511;

    for (int j = tid; j < NPART; j += 256) {
        int gj = b * NPART + j;
        float vx = v0[gj * 2], vy = v0[gj * 2 + 1];
        sx[j] = p0[gj * 2 + 0] + vx + 0.5f * a[gj * 2 + 0];
        sy[j] = p0[gj * 2 + 1] + vy + 0.5f * a[gj * 2 + 1];
        smk[j] = mask[gj];
    }
    if (tid < 16) cnt[tid] = 0;

    if (tid < 128) {
        int c = tid >> 3, m = tid & 7;
        float v0x = v0[bi * 2 + 0], v0y = v0[bi * 2 + 1];
        float ax = a[bi * 2 + 0], ay = a[bi * 2 + 1];
        float v1x = v0x + ax, v1y = v0y + ay;
        float p1x = p0[bi * 2 + 0] + 0.5f * (v0x + v1x);
        float p1y = p0[bi * 2 + 1] + 0.5f * (v0y + v1y);
        float x, y;
        if (c == 0)      { x = v1x; y = v1y; }
        else if (c == 1) { x = p1x; y = p1y; }
        else if (c < 9)  { int t = c - 2; x = v0_enc[(bi * 7 + t) * 2 + 0]; y = v0_enc[(bi * 7 + t) * 2 + 1]; }
        else             { int t = c - 9; x = p0_enc[(bi * 7 + t) * 2 + 0]; y = p0_enc[(bi * 7 + t) * 2 + 1]; }
        float th = (float)m * 0.78539816339744831f;
        float cs = cosf(th), sn = sinf(th);
        float lc0 = lc[0], lc1 = lc[1], ld0 = ld[0], ld1 = ld[1];
        g_regC[bi * 128 + tid] = x * (lc0 * cs - lc1 * sn) + y * (lc0 * sn + lc1 * cs);
        g_regD[bi * 128 + tid] = x * (ld0 * cs - ld1 * sn) + y * (ld0 * sn + ld1 * cs);
    }
    __syncthreads();
    if (tid == 0) { g_p1[bi * 2] = sx[i]; g_p1[bi * 2 + 1] = sy[i]; }
    float xi = sx[i], yi = sy[i];

    float part = 0.f;
    for (int j = tid; j < NPART; j += 256) {
        float rx = sx[j] - xi, ry = sy[j] - yi;
        float d2 = (rx * rx + ry * ry + 1e-12f) * (0.025f * 0.025f);
        float u = fmaxf(1.f - d2, 0.f);
        float w = u * u * u * smk[j];
        sw[j] = w;
        part += w;
    }
    red[tid] = part;
    __syncthreads();
    for (int s = 128; s > 0; s >>= 1) { if (tid < s) red[tid] += red[tid + s]; __syncthreads(); }
    float inv = 1.f / (red[0] + 1e-6f);
    __syncthreads();

    float4 eloc[2];
    int tloc[2];
    int nloc = 0;
#pragma unroll
    for (int c = 0; c < 2; ++c) {
        int j = c * 256 + tid;
        float w = sw[j];
        if (w > 0.f) {
            float rx = sx[j] - xi, ry = sy[j] - yi;
            float d = sqrtf(rx * rx + ry * ry + 1e-12f) * 0.025f;
            float wb = w * inv;
            float rc = fminf(fmaxf(d * 3.f - 0.5f, 0.f), 2.f);
            float r0 = floorf(rc);
            float wr = rc - r0;
            int r0i = (int)r0;
            float axv = (j == i) ? 1.f : rx;
            float ayv = (j == i) ? 0.f : ry;
            float ang = atan2f(ayv, axv);
            ang = ang - TWO_PI * floorf(ang * INV_2PI);
            float tc = ang * (16.f * INV_2PI);
            float t0 = floorf(tc);
            float wt = tc - t0;
            int t0i = ((int)t0) & 15;
            eloc[nloc] = make_float4(wb * (1.f - wr), wb * wr, wt,
                                     __int_as_float(j | (r0i << 16)));
            tloc[nloc] = t0i;
            ++nloc;
            atomicAdd(&cnt[t0i], 1);
        }
    }
    __syncthreads();
    if (tid == 0) {
        int s = 0;
        for (int g = 0; g < 16; ++g) { bstart[g] = s; s += cnt[g]; }
        bstart[16] = s;
    }
    __syncthreads();
    if (tid < 16) offs[tid] = bstart[tid];
    if (tid < 17) g_binStart[bi * 17 + tid] = bstart[tid];
    __syncthreads();

    float4* ent = g_ent + (size_t)bi * 512;
    for (int l = 0; l < nloc; ++l) {
        int pos = atomicAdd(&offs[tloc[l]], 1);
        ent[pos] = eloc[l];
    }
}

// ---------------- stage 1: t-column CSR gather + dense tail copy ----------------
// srcsel/dsel: 0 = g_regC/g_regD, 1 = g_actA, 2 = g_actB
template <int CK>
__global__ void __launch_bounds__(512) stage1_kernel(int srcsel, int dsel) {
    const int V2 = CK / 64;
    const int KDP = 49 * CK;
    int bi = blockIdx.x;
    int b = bi >> 9;
    int tid = threadIdx.x;
    int warp = tid >> 5, lane = tid & 31;
    const float* __restrict__ feats = (srcsel == 0) ? g_regC : (srcsel == 1) ? g_actA : g_actB;
    const float* __restrict__ dsrc  = (dsel == 0) ? g_regD : (dsel == 1) ? g_actA : g_actB;

    __shared__ int bs[17];
    if (tid < 17) bs[tid] = g_binStart[bi * 17 + tid];
    __syncthreads();

    // dense tail copy: F[bi][48*CK + cn] = densein[bi][cn]
    float* Fb = g_F + (size_t)bi * KDP;
    for (int x = tid; x < CK; x += 512)
        Fb[48 * CK + x] = dsrc[(size_t)bi * CK + x];

    const float4* __restrict__ ent = g_ent + (size_t)bi * 512;
    const float* __restrict__ fb = feats + (size_t)b * NPART * CK;

    unsigned long long a0[V2], a1[V2], a2[V2];
#pragma unroll
    for (int v = 0; v < V2; ++v) { a0[v] = 0ull; a1[v] = 0ull; a2[v] = 0ull; }

#pragma unroll
    for (int list = 0; list < 2; ++list) {
        int col = (list == 0) ? warp : ((warp + 15) & 15);
        int s = bs[col], e = bs[col + 1];
        for (int k = s; k < e; ++k) {
            float4 m = ent[k];
            int jr = __float_as_int(m.w);
            int j = jr & 511;
            int r0 = jr >> 16;
            float wtp = (list == 0) ? (1.f - m.z) : m.z;
            float w0 = m.x * wtp, w1 = m.y * wtp;
            float cr0 = (r0 == 0) ? w0 : 0.f;
            float cr1 = (r0 == 0) ? w1 : ((r0 == 1) ? w0 : 0.f);
            float cr2 = (r0 == 1) ? w1 : ((r0 == 2) ? (w0 + w1) : 0.f);
            unsigned long long p0 = pack2(cr0), p1 = pack2(cr1), p2 = pack2(cr2);
            if (V2 == 2) {
                F4U f;
                f.f4 = *(const float4*)(fb + j * CK + lane * 4);
                a0[0] = ffma2(p0, f.u2[0], a0[0]);
                a0[1] = ffma2(p0, f.u2[1], a0[1]);
                a1[0] = ffma2(p1, f.u2[0], a1[0]);
                a1[1] = ffma2(p1, f.u2[1], a1[1]);
                a2[0] = ffma2(p2, f.u2[0], a2[0]);
                a2[1] = ffma2(p2, f.u2[1], a2[1]);
            } else {
                F2U f;
                f.f2 = *(const float2*)(fb + j * CK + lane * 2);
                a0[0] = ffma2(p0, f.u2, a0[0]);
                a1[0] = ffma2(p1, f.u2, a1[0]);
                a2[0] = ffma2(p2, f.u2, a2[0]);
            }
        }
    }

    if (V2 == 2) {
        F4U o0, o1, o2;
        o0.u2[0] = a0[0]; o0.u2[1] = a0[1];
        o1.u2[0] = a1[0]; o1.u2[1] = a1[1];
        o2.u2[0] = a2[0]; o2.u2[1] = a2[1];
        *(float4*)(Fb + (0 * 16 + warp) * CK + lane * 4) = o0.f4;
        *(float4*)(Fb + (1 * 16 + warp) * CK + lane * 4) = o1.f4;
        *(float4*)(Fb + (2 * 16 + warp) * CK + lane * 4) = o2.f4;
    } else {
        F2U o0, o1, o2;
        o0.u2 = a0[0]; o1.u2 = a1[0]; o2.u2 = a2[0];
        *(float2*)(Fb + (0 * 16 + warp) * CK + lane * 2) = o0.f2;
        *(float2*)(Fb + (1 * 16 + warp) * CK + lane * 2) = o1.f2;
        *(float2*)(Fb + (2 * 16 + warp) * CK + lane * 2) = o2.f2;
    }
}

// ---------------- stage 2a: split-K GEMM (conv+dense merged) ----------------
template <int OK, int TM, int ROWS, int CPT, int KS>
__global__ void __launch_bounds__((TM / ROWS) * (OK / CPT)) gemm_kernel(int KD, int wOff) {
    const int KB = 32;
    const int THREADS = (TM / ROWS) * (OK / CPT);
    const int NW4 = (KB * OK / 4 + THREADS - 1) / THREADS;
    const int NF4 = (TM * KB / 4 + THREADS - 1) / THREADS;
    __shared__ __align__(16) float Wt[KB * OK];
    __shared__ __align__(16) float Ft[TM * KB];
    int tid = threadIdx.x;
    int i0 = blockIdx.x * TM;
    int KC = KD / KS;
    int k0 = blockIdx.y * KC;
    int NCH = KC / KB;

    const float* Wsrc = g_Wbig + wOff + (size_t)k0 * OK;

    float4 wreg[NW4], freg[NF4];
    {
        const float4* src = (const float4*)Wsrc;
#pragma unroll
        for (int u = 0; u < NW4; ++u) {
            int x = tid + u * THREADS;
            if (x < KB * OK / 4) wreg[u] = src[x];
        }
#pragma unroll
        for (int u = 0; u < NF4; ++u) {
            int x = tid + u * THREADS;
            if (x < TM * KB / 4) {
                int row = x / (KB / 4), kc = x % (KB / 4);
                freg[u] = *(const float4*)(g_F + (size_t)(i0 + row) * KD + k0 + kc * 4);
            }
        }
    }

    int rg = tid / (OK / CPT);
    int cg = (tid % (OK / CPT)) * CPT;
    unsigned long long accp[ROWS][CPT / 2];
#pragma unroll
    for (int r = 0; r < ROWS; ++r)
#pragma unroll
        for (int c = 0; c < CPT / 2; ++c) accp[r][c] = 0ull;

    for (int ch = 0; ch < NCH; ++ch) {
        __syncthreads();
#pragma unroll
        for (int u = 0; u < NW4; ++u) {
            int x = tid + u * THREADS;
            if (x < KB * OK / 4) ((float4*)Wt)[x] = wreg[u];
        }
#pragma unroll
        for (int u = 0; u < NF4; ++u) {
            int x = tid + u * THREADS;
            if (x < TM * KB / 4) ((float4*)Ft)[x] = freg[u];
        }
        __syncthreads();
        if (ch + 1 < NCH) {
            const float4* src = (const float4*)(Wsrc + (size_t)(ch + 1) * KB * OK);
#pragma unroll
            for (int u = 0; u < NW4; ++u) {
                int x = tid + u * THREADS;
                if (x < KB * OK / 4) wreg[u] = src[x];
            }
#pragma unroll
            for (int u = 0; u < NF4; ++u) {
                int x = tid + u * THREADS;
                if (x < TM * KB / 4) {
                    int rr = x / (KB / 4), kc = x % (KB / 4);
                    freg[u] = *(const float4*)(g_F + (size_t)(i0 + rr) * KD + k0 + (ch + 1) * KB + kc * 4);
                }
            }
        }
#pragma unroll 4
        for (int k = 0; k < KB; ++k) {
            unsigned long long fp[ROWS];
#pragma unroll
            for (int r = 0; r < ROWS; ++r)
                fp[r] = pack2(Ft[(rg * ROWS + r) * KB + k]);
#pragma unroll
            for (int c = 0; c < CPT; c += 4) {
                F4U w;
                w.f4 = *(const float4*)&Wt[k * OK + cg + c];
#pragma unroll
                for (int r = 0; r < ROWS; ++r) {
                    accp[r][c / 2]     = ffma2(fp[r], w.u2[0], accp[r][c / 2]);
                    accp[r][c / 2 + 1] = ffma2(fp[r], w.u2[1], accp[r][c / 2 + 1]);
                }
            }
        }
    }

#pragma unroll
    for (int r = 0; r < ROWS; ++r) {
        float* dst = g_part + ((size_t)blockIdx.y * BN + i0 + rg * ROWS + r) * OK + cg;
#pragma unroll
        for (int c = 0; c < CPT; c += 4) {
            F4U o;
            o.u2[0] = accp[r][c / 2];
            o.u2[1] = accp[r][c / 2 + 1];
            *(float4*)&dst[c] = o.f4;
        }
    }
}

// ---------------- stage 2b: sum partials + epilogue (no dense dot) ----------------
// modes: 1 = write+act, 2 = +residual, 3 = last (split oc/od)
template <int OK, int ROWS, int KS>
__global__ void __launch_bounds__(OK * ROWS) reduce_kernel(int mode, int aout) {
    int tid = threadIdx.x;
    int row = tid / OK, om = tid % OK;
    int bi = blockIdx.x * ROWS + row;

    float v = 0.f;
#pragma unroll
    for (int ks = 0; ks < KS; ++ks)
        v += g_part[((size_t)ks * BN + bi) * OK + om];

    if (mode == 3) {
        if (om < 24) g_oc[bi * 24 + om] = v;
        else         g_od[bi * 24 + om - 24] = v;
        return;
    }

    float* __restrict__ actout = (aout == 1) ? g_actA : g_actB;
    if (mode == 2) v += g_out[bi * OK + om];
    g_out[bi * OK + om] = v;
    float sq = v * v;
    sq += __shfl_xor_sync(0xffffffffu, sq, 1);
    sq += __shfl_xor_sync(0xffffffffu, sq, 2);
    sq += __shfl_xor_sync(0xffffffffu, sq, 4);
    float mg = sq + 1e-6f;
    actout[bi * OK + om] = v / mg * fmaxf(mg - 0.2f, 0.f);
}

// ---------------- final projection + correction ----------------
__global__ void final_kernel(const float* __restrict__ p0,
                             const float* __restrict__ pc,
                             const float* __restrict__ pd,
                             float* __restrict__ outp) {
    int bi = blockIdx.x * blockDim.x + threadIdx.x;
    if (bi >= BN) return;
    float res[3][2] = {{0.f, 0.f}, {0.f, 0.f}, {0.f, 0.f}};
    float c0 = pc[0], c1 = pc[1], d0 = pd[0], d1 = pd[1];
#pragma unroll
    for (int m = 0; m < 8; ++m) {
        float th = (float)m * 0.78539816339744831f;
        float cs = cosf(th), sn = sinf(th);
        float Mc0 = c0 * cs - c1 * sn, Mc1 = c0 * sn + c1 * cs;
        float Md0 = d0 * cs - d1 * sn, Md1 = d0 * sn + d1 * cs;
#pragma unroll
        for (int ch = 0; ch < 3; ++ch) {
            float vc = g_oc[bi * 24 + ch * 8 + m];
            float vd = g_od[bi * 24 + ch * 8 + m];
            res[ch][0] += vc * Mc0 + vd * Md0;
            res[ch][1] += vc * Mc1 + vd * Md1;
        }
    }
    const float CORR = 1.0f / 128.0f;
    float pcx = g_p1[bi * 2 + 0] + CORR * res[0][0];
    float pcy = g_p1[bi * 2 + 1] + CORR * res[0][1];
    outp[bi * 2 + 0] = pcx;
    outp[bi * 2 + 1] = pcy;
    outp[BN * 2 + bi * 2 + 0] = pcx - p0[bi * 2 + 0];
    outp[BN * 2 + bi * 2 + 1] = pcy - p0[bi * 2 + 1];
    outp[BN * 4 + bi * 4 + 0] = CORR * res[1][0];
    outp[BN * 4 + bi * 4 + 1] = CORR * res[1][1];
    outp[BN * 4 + bi * 4 + 2] = CORR * res[2][0];
    outp[BN * 4 + bi * 4 + 3] = CORR * res[2][1];
}

// ---------------- launch ----------------
extern "C" void kernel_launch(void* const* d_in, const int* in_sizes, int n_in,
                              void* d_out, int out_size) {
    const float* p0_enc  = (const float*)d_in[0];
    const float* v0_enc  = (const float*)d_in[1];
    const float* p0      = (const float*)d_in[2];
    const float* v0      = (const float*)d_in[3];
    const float* a       = (const float*)d_in[4];
    const float* mask    = (const float*)d_in[5];
    const float* lift_c0 = (const float*)d_in[6];
    const float* Wc0     = (const float*)d_in[7];
    const float* lift_d0 = (const float*)d_in[8];
    const float* Wd0     = (const float*)d_in[9];
    const float* Wc1     = (const float*)d_in[10];
    const float* Wd1     = (const float*)d_in[11];
    const float* Wc2     = (const float*)d_in[12];
    const float* Wd2     = (const float*)d_in[13];
    const float* Wc3     = (const float*)d_in[14];
    const float* Wd3     = (const float*)d_in[15];
    const float* Wc4     = (const float*)d_in[16];
    const float* proj_c4 = (const float*)d_in[17];
    const float* Wd4     = (const float*)d_in[18];
    const float* proj_d4 = (const float*)d_in[19];

    const int NEXP = (1555456 + 255) / 256;
    prep_kernel<<<BN + NEXP, 256>>>(mask, p0, v0, a, p0_enc, v0_enc,
                                    lift_c0, lift_d0,
                                    Wc0, Wc1, Wc2, Wc3, Wc4,
                                    Wd0, Wd1, Wd2, Wd3, Wd4);

    const int wOff[5] = {0, 401408, 602112, 1003520, 1404928};

    // act ping-pong: L0 -> A; L1: A->B; L2: B->A; L3: A->B; L4: reads B
    // KDp = 49*CK: 6272 (CK=128) / 3136 (CK=64); all layers: KC=224, NCH=7
    // L0: CK=128, OKt=64 (conv 0-31 | dense 32-63)
    stage1_kernel<128><<<BN, 512>>>(0, 0);
    gemm_kernel<64, 128, 2, 8, 28><<<dim3(8, 28), 512>>>(6272, wOff[0]);
    reduce_kernel<64, 4, 28><<<BN / 4, 256>>>(1, 1);
    // L1: CK=64, OKt=64 merged, residual
    stage1_kernel<64><<<BN, 512>>>(1, 1);
    gemm_kernel<64, 64, 2, 8, 14><<<dim3(16, 14), 256>>>(3136, wOff[1]);
    reduce_kernel<64, 4, 14><<<BN / 4, 256>>>(2, 2);
    // L2: CK=64, OKt=128 merged
    stage1_kernel<64><<<BN, 512>>>(2, 2);
    gemm_kernel<128, 32, 2, 8, 14><<<dim3(32, 14), 256>>>(3136, wOff[2]);
    reduce_kernel<128, 2, 14><<<BN / 2, 256>>>(1, 1);
    // L3: CK=128, OKt=64 merged
    stage1_kernel<128><<<BN, 512>>>(1, 1);
    gemm_kernel<64, 64, 2, 8, 28><<<dim3(16, 28), 256>>>(6272, wOff[3]);
    reduce_kernel<64, 4, 28><<<BN / 4, 256>>>(1, 2);
    // L4: CK=64, OKt=48 (conv 0-23 | dense 24-47), last
    stage1_kernel<64><<<BN, 512>>>(2, 2);
    gemm_kernel<48, 128, 2, 8, 14><<<dim3(8, 14), 384>>>(3136, wOff[4]);
    reduce_kernel<48, 8, 14><<<BN / 8, 384>>>(3, 2);

    final_kernel<<<4, 256>>>(p0, proj_c4, proj_d4, (float*)d_out);
}

// round 12
// speedup vs baseline: 1.0814x; 1.0814x over previous
#include <cuda_runtime.h>

#define B_     2
#define NPART  512
#define BN     1024
#define GBINS  48
#define TWO_PI 6.283185307179586f
#define INV_2PI 0.15915494309189535f

// ---------------- static device scratch ----------------
__device__ float    g_p1[BN * 2];
__device__ float    g_regC[BN * 128];
__device__ float    g_regD[BN * 128];
__device__ float4   g_ent[BN * 1024];         // 2 entries/neighbor: (cr0, cr1, cr2, j)
__device__ int      g_binStart[BN * 17];      // CSR over 16 t-columns
__device__ float    g_F[BN * GBINS * 128];
__device__ float    g_out[BN * 128];
__device__ float    g_actA[BN * 128];
__device__ float    g_actB[BN * 128];
__device__ float    g_Wbig[1253376];
__device__ float    g_WdT[26112];
__device__ float    g_part[16 * BN * 64];     // split-K partials
__device__ float    g_oc[BN * 24];
__device__ float    g_od[BN * 24];

__constant__ int c_wOff[6] = {0, 196608, 393216, 786432, 1179648, 1253376};
__constant__ int c_dOff[6] = {0, 4096, 8192, 16384, 24576, 26112};

// ---------------- f32x2 helpers ----------------
__device__ __forceinline__ unsigned long long pack2(float x) {
    unsigned long long r;
    asm("mov.b64 %0, {%1, %1};" : "=l"(r) : "f"(x));
    return r;
}
__device__ __forceinline__ unsigned long long ffma2(unsigned long long a,
                                                    unsigned long long b,
                                                    unsigned long long c) {
    unsigned long long d;
    asm("fma.rn.f32x2 %0, %1, %2, %3;" : "=l"(d) : "l"(a), "l"(b), "l"(c));
    return d;
}
union F4U { float4 f4; float f[4]; unsigned long long u2[2]; };
union F2U { float2 f2; unsigned long long u2; };

// ---------------- prep: geom+lift (blocks 0..BN-1) and expand (rest) ----------------
__global__ void __launch_bounds__(256) prep_kernel(
        const float* __restrict__ mask, const float* __restrict__ p0,
        const float* __restrict__ v0, const float* __restrict__ a,
        const float* __restrict__ p0_enc, const float* __restrict__ v0_enc,
        const float* __restrict__ lc, const float* __restrict__ ld,
        const float* __restrict__ Wc0, const float* __restrict__ Wc1,
        const float* __restrict__ Wc2, const float* __restrict__ Wc3,
        const float* __restrict__ Wc4,
        const float* __restrict__ Wd0, const float* __restrict__ Wd1,
        const float* __restrict__ Wd2, const float* __restrict__ Wd3,
        const float* __restrict__ Wd4) {
    int tid = threadIdx.x;
    if (blockIdx.x >= BN) {
        const int Cs[5] = {16, 8, 8, 16, 8};
        const int Os[5] = {4, 8, 16, 8, 3};
        int idx = (blockIdx.x - BN) * 256 + tid;
        if (idx < 1253376) {
            int l = 0;
            while (idx >= c_wOff[l + 1]) ++l;
            int loc = idx - c_wOff[l];
            const float* Wc = (l == 0) ? Wc0 : (l == 1) ? Wc1 : (l == 2) ? Wc2 : (l == 3) ? Wc3 : Wc4;
            int C = Cs[l], OK = Os[l] * 8;
            int om = loc % OK;
            int kk = loc / OK;
            int n = kk & 7;
            int c = (kk >> 3) % C;
            int g = (kk >> 3) / C;
            int r = g >> 4, t = g & 15;
            int o = om >> 3, m = om & 7;
            g_Wbig[idx] = Wc[(((o * C + c) * 8 + ((n - m) & 7)) * 3 + r) * 16 + ((t - 2 * m) & 15)];
        } else if (idx < 1253376 + 26112) {
            int id2 = idx - 1253376;
            int l = 0;
            while (id2 >= c_dOff[l + 1]) ++l;
            int loc = id2 - c_dOff[l];
            const float* Wd = (l == 0) ? Wd0 : (l == 1) ? Wd1 : (l == 2) ? Wd2 : (l == 3) ? Wd3 : Wd4;
            int C = Cs[l], OK = Os[l] * 8;
            int om = loc % OK;
            int cn = loc / OK;
            int o = om >> 3, m = om & 7, c = cn >> 3, n = cn & 7;
            g_WdT[id2] = Wd[(o * C + c) * 8 + ((m - n) & 7)];
        }
        return;
    }

    __shared__ float sx[NPART], sy[NPART], smk[NPART], sw[NPART];
    __shared__ float red[256];
    __shared__ int cnt[16], offs[16], bstart[17];
    int bi = blockIdx.x;
    int b = bi >> 9, i = bi & 511;

    for (int j = tid; j < NPART; j += 256) {
        int gj = b * NPART + j;
        float vx = v0[gj * 2], vy = v0[gj * 2 + 1];
        sx[j] = p0[gj * 2 + 0] + vx + 0.5f * a[gj * 2 + 0];
        sy[j] = p0[gj * 2 + 1] + vy + 0.5f * a[gj * 2 + 1];
        smk[j] = mask[gj];
    }
    if (tid < 16) cnt[tid] = 0;

    if (tid < 128) {
        int c = tid >> 3, m = tid & 7;
        float v0x = v0[bi * 2 + 0], v0y = v0[bi * 2 + 1];
        float ax = a[bi * 2 + 0], ay = a[bi * 2 + 1];
        float v1x = v0x + ax, v1y = v0y + ay;
        float p1x = p0[bi * 2 + 0] + 0.5f * (v0x + v1x);
        float p1y = p0[bi * 2 + 1] + 0.5f * (v0y + v1y);
        float x, y;
        if (c == 0)      { x = v1x; y = v1y; }
        else if (c == 1) { x = p1x; y = p1y; }
        else if (c < 9)  { int t = c - 2; x = v0_enc[(bi * 7 + t) * 2 + 0]; y = v0_enc[(bi * 7 + t) * 2 + 1]; }
        else             { int t = c - 9; x = p0_enc[(bi * 7 + t) * 2 + 0]; y = p0_enc[(bi * 7 + t) * 2 + 1]; }
        float th = (float)m * 0.78539816339744831f;
        float cs = cosf(th), sn = sinf(th);
        float lc0 = lc[0], lc1 = lc[1], ld0 = ld[0], ld1 = ld[1];
        g_regC[bi * 128 + tid] = x * (lc0 * cs - lc1 * sn) + y * (lc0 * sn + lc1 * cs);
        g_regD[bi * 128 + tid] = x * (ld0 * cs - ld1 * sn) + y * (ld0 * sn + ld1 * cs);
    }
    __syncthreads();
    if (tid == 0) { g_p1[bi * 2] = sx[i]; g_p1[bi * 2 + 1] = sy[i]; }
    float xi = sx[i], yi = sy[i];

    float part = 0.f;
    for (int j = tid; j < NPART; j += 256) {
        float rx = sx[j] - xi, ry = sy[j] - yi;
        float d2 = (rx * rx + ry * ry + 1e-12f) * (0.025f * 0.025f);
        float u = fmaxf(1.f - d2, 0.f);
        float w = u * u * u * smk[j];
        sw[j] = w;
        part += w;
    }
    red[tid] = part;
    __syncthreads();
    for (int s = 128; s > 0; s >>= 1) { if (tid < s) red[tid] += red[tid + s]; __syncthreads(); }
    float inv = 1.f / (red[0] + 1e-6f);
    __syncthreads();

    // 2 entries per in-range neighbor, fully resolved radial weights
    float4 eloc[4];
    int tloc[4];
    int nloc = 0;
#pragma unroll
    for (int c = 0; c < 2; ++c) {
        int j = c * 256 + tid;
        float w = sw[j];
        if (w > 0.f) {
            float rx = sx[j] - xi, ry = sy[j] - yi;
            float d = sqrtf(rx * rx + ry * ry + 1e-12f) * 0.025f;
            float wb = w * inv;
            float rc = fminf(fmaxf(d * 3.f - 0.5f, 0.f), 2.f);
            float r0 = floorf(rc);
            float wr = rc - r0;
            int r0i = (int)r0;
            float w0 = wb * (1.f - wr), w1 = wb * wr;
            float b0, b1, b2;
            if (r0i == 0)      { b0 = w0; b1 = w1; b2 = 0.f; }
            else if (r0i == 1) { b0 = 0.f; b1 = w0; b2 = w1; }
            else               { b0 = 0.f; b1 = 0.f; b2 = w0 + w1; }
            float axv = (j == i) ? 1.f : rx;
            float ayv = (j == i) ? 0.f : ry;
            float ang = atan2f(ayv, axv);
            ang = ang - TWO_PI * floorf(ang * INV_2PI);
            float tc = ang * (16.f * INV_2PI);
            float t0 = floorf(tc);
            float wt = tc - t0;
            int t0i = ((int)t0) & 15;
            int t1i = (t0i + 1) & 15;
            float jf = __int_as_float(j);
            float u0 = 1.f - wt;
            eloc[nloc] = make_float4(b0 * u0, b1 * u0, b2 * u0, jf);
            tloc[nloc] = t0i;
            ++nloc;
            atomicAdd(&cnt[t0i], 1);
            eloc[nloc] = make_float4(b0 * wt, b1 * wt, b2 * wt, jf);
            tloc[nloc] = t1i;
            ++nloc;
            atomicAdd(&cnt[t1i], 1);
        }
    }
    __syncthreads();
    if (tid == 0) {
        int s = 0;
        for (int g = 0; g < 16; ++g) { bstart[g] = s; s += cnt[g]; }
        bstart[16] = s;
    }
    __syncthreads();
    if (tid < 16) offs[tid] = bstart[tid];
    if (tid < 17) g_binStart[bi * 17 + tid] = bstart[tid];
    __syncthreads();

    float4* ent = g_ent + (size_t)bi * 1024;
    for (int l = 0; l < nloc; ++l) {
        int pos = atomicAdd(&offs[tloc[l]], 1);
        ent[pos] = eloc[l];
    }
}

// ---------------- stage 1: single-list t-column gather, resolved weights ----------------
template <int CK>
__global__ void __launch_bounds__(512) stage1_kernel(int srcsel) {
    const int V2 = CK / 64;
    int bi = blockIdx.x;
    int b = bi >> 9;
    int tid = threadIdx.x;
    int warp = tid >> 5, lane = tid & 31;
    const float* __restrict__ feats = (srcsel == 0) ? g_regC : (srcsel == 1) ? g_actA : g_actB;

    __shared__ int bs[17];
    if (tid < 17) bs[tid] = g_binStart[bi * 17 + tid];
    __syncthreads();

    const float4* __restrict__ ent = g_ent + (size_t)bi * 1024;
    const float* __restrict__ fb = feats + (size_t)b * NPART * CK;

    unsigned long long a0[V2], a1[V2], a2[V2];
#pragma unroll
    for (int v = 0; v < V2; ++v) { a0[v] = 0ull; a1[v] = 0ull; a2[v] = 0ull; }

    int s = bs[warp], e = bs[warp + 1];
    for (int k = s; k < e; ++k) {
        float4 m = ent[k];
        int j = __float_as_int(m.w);
        unsigned long long p0 = pack2(m.x), p1 = pack2(m.y), p2 = pack2(m.z);
        if (V2 == 2) {
            F4U f;
            f.f4 = *(const float4*)(fb + j * CK + lane * 4);
            a0[0] = ffma2(p0, f.u2[0], a0[0]);
            a0[1] = ffma2(p0, f.u2[1], a0[1]);
            a1[0] = ffma2(p1, f.u2[0], a1[0]);
            a1[1] = ffma2(p1, f.u2[1], a1[1]);
            a2[0] = ffma2(p2, f.u2[0], a2[0]);
            a2[1] = ffma2(p2, f.u2[1], a2[1]);
        } else {
            F2U f;
            f.f2 = *(const float2*)(fb + j * CK + lane * 2);
            a0[0] = ffma2(p0, f.u2, a0[0]);
            a1[0] = ffma2(p1, f.u2, a1[0]);
            a2[0] = ffma2(p2, f.u2, a2[0]);
        }
    }

    float* Fb = g_F + (size_t)bi * GBINS * CK;
    if (V2 == 2) {
        F4U o0, o1, o2;
        o0.u2[0] = a0[0]; o0.u2[1] = a0[1];
        o1.u2[0] = a1[0]; o1.u2[1] = a1[1];
        o2.u2[0] = a2[0]; o2.u2[1] = a2[1];
        *(float4*)(Fb + (0 * 16 + warp) * CK + lane * 4) = o0.f4;
        *(float4*)(Fb + (1 * 16 + warp) * CK + lane * 4) = o1.f4;
        *(float4*)(Fb + (2 * 16 + warp) * CK + lane * 4) = o2.f4;
    } else {
        F2U o0, o1, o2;
        o0.u2 = a0[0]; o1.u2 = a1[0]; o2.u2 = a2[0];
        *(float2*)(Fb + (0 * 16 + warp) * CK + lane * 2) = o0.f2;
        *(float2*)(Fb + (1 * 16 + warp) * CK + lane * 2) = o1.f2;
        *(float2*)(Fb + (2 * 16 + warp) * CK + lane * 2) = o2.f2;
    }
}

// ---------------- stage 2a: split-K GEMM (partials only) ----------------
template <int OK, int TM, int ROWS, int CPT, int KS>
__global__ void __launch_bounds__((TM / ROWS) * (OK / CPT)) gemm_kernel(int KD, int wOff) {
    const int KB = 32;
    const int THREADS = (TM / ROWS) * (OK / CPT);
    const int NW4 = (KB * OK / 4 + THREADS - 1) / THREADS;
    const int NF4 = (TM * KB / 4 + THREADS - 1) / THREADS;
    __shared__ __align__(16) float Wt[KB * OK];
    __shared__ __align__(16) float Ft[TM * KB];
    int tid = threadIdx.x;
    int i0 = blockIdx.x * TM;
    int KC = KD / KS;
    int k0 = blockIdx.y * KC;
    int NCH = KC / KB;

    const float* Wsrc = g_Wbig + wOff + (size_t)k0 * OK;

    float4 wreg[NW4], freg[NF4];
    {
        const float4* src = (const float4*)Wsrc;
#pragma unroll
        for (int u = 0; u < NW4; ++u) {
            int x = tid + u * THREADS;
            if (x < KB * OK / 4) wreg[u] = src[x];
        }
#pragma unroll
        for (int u = 0; u < NF4; ++u) {
            int x = tid + u * THREADS;
            if (x < TM * KB / 4) {
                int row = x / (KB / 4), kc = x % (KB / 4);
                freg[u] = *(const float4*)(g_F + (size_t)(i0 + row) * KD + k0 + kc * 4);
            }
        }
    }

    int rg = tid / (OK / CPT);
    int cg = (tid % (OK / CPT)) * CPT;
    unsigned long long accp[ROWS][CPT / 2];
#pragma unroll
    for (int r = 0; r < ROWS; ++r)
#pragma unroll
        for (int c = 0; c < CPT / 2; ++c) accp[r][c] = 0ull;

    for (int ch = 0; ch < NCH; ++ch) {
        __syncthreads();
#pragma unroll
        for (int u = 0; u < NW4; ++u) {
            int x = tid + u * THREADS;
            if (x < KB * OK / 4) ((float4*)Wt)[x] = wreg[u];
        }
#pragma unroll
        for (int u = 0; u < NF4; ++u) {
            int x = tid + u * THREADS;
            if (x < TM * KB / 4) ((float4*)Ft)[x] = freg[u];
        }
        __syncthreads();
        if (ch + 1 < NCH) {
            const float4* src = (const float4*)(Wsrc + (size_t)(ch + 1) * KB * OK);
#pragma unroll
            for (int u = 0; u < NW4; ++u) {
                int x = tid + u * THREADS;
                if (x < KB * OK / 4) wreg[u] = src[x];
            }
#pragma unroll
            for (int u = 0; u < NF4; ++u) {
                int x = tid + u * THREADS;
                if (x < TM * KB / 4) {
                    int rr = x / (KB / 4), kc = x % (KB / 4);
                    freg[u] = *(const float4*)(g_F + (size_t)(i0 + rr) * KD + k0 + (ch + 1) * KB + kc * 4);
                }
            }
        }
#pragma unroll 4
        for (int k = 0; k < KB; ++k) {
            unsigned long long fp[ROWS];
#pragma unroll
            for (int r = 0; r < ROWS; ++r)
                fp[r] = pack2(Ft[(rg * ROWS + r) * KB + k]);
#pragma unroll
            for (int c = 0; c < CPT; c += 4) {
                F4U w;
                w.f4 = *(const float4*)&Wt[k * OK + cg + c];
#pragma unroll
                for (int r = 0; r < ROWS; ++r) {
                    accp[r][c / 2]     = ffma2(fp[r], w.u2[0], accp[r][c / 2]);
                    accp[r][c / 2 + 1] = ffma2(fp[r], w.u2[1], accp[r][c / 2 + 1]);
                }
            }
        }
    }

#pragma unroll
    for (int r = 0; r < ROWS; ++r) {
        float* dst = g_part + ((size_t)blockIdx.y * BN + i0 + rg * ROWS + r) * OK + cg;
#pragma unroll
        for (int c = 0; c < CPT; c += 4) {
            F4U o;
            o.u2[0] = accp[r][c / 2];
            o.u2[1] = accp[r][c / 2 + 1];
            *(float4*)&dst[c] = o.f4;
        }
    }
}

// ---------------- stage 2b: deterministic reduce + dense + epilogue ----------------
template <int OK, int ROWS, int KS, int CK>
__global__ void __launch_bounds__(OK * ROWS) reduce_kernel(int mode, int dOff,
                                                           int ain, int aout) {
    int tid = threadIdx.x;
    int row = tid / OK, om = tid % OK;
    int bi = blockIdx.x * ROWS + row;

    float oc = 0.f;
#pragma unroll
    for (int ks = 0; ks < KS; ++ks)
        oc += g_part[((size_t)ks * BN + bi) * OK + om];

    const float* __restrict__ densein = (ain == 0) ? g_regD : (ain == 1) ? g_actA : g_actB;
    float* __restrict__ actout = (aout == 1) ? g_actA : g_actB;
    const float* WdT = g_WdT + dOff;
    const float* x = densein + (size_t)bi * CK;
    float od = 0.f;
#pragma unroll 8
    for (int cn = 0; cn < CK; ++cn) od = fmaf(x[cn], WdT[cn * OK + om], od);

    if (mode == 0) {
        g_out[bi * 64 + om] = oc;
        g_out[bi * 64 + 32 + om] = od;
        float sc = oc * oc;
        sc += __shfl_xor_sync(0xffffffffu, sc, 1);
        sc += __shfl_xor_sync(0xffffffffu, sc, 2);
        sc += __shfl_xor_sync(0xffffffffu, sc, 4);
        float mc = sc + 1e-6f;
        actout[bi * 64 + om] = oc / mc * fmaxf(mc - 0.2f, 0.f);
        float sd = od * od;
        sd += __shfl_xor_sync(0xffffffffu, sd, 1);
        sd += __shfl_xor_sync(0xffffffffu, sd, 2);
        sd += __shfl_xor_sync(0xffffffffu, sd, 4);
        float md = sd + 1e-6f;
        actout[bi * 64 + 32 + om] = od / md * fmaxf(md - 0.2f, 0.f);
    } else if (mode == 3) {
        g_oc[bi * 24 + om] = oc;
        g_od[bi * 24 + om] = od;
    } else {
        float v = oc + od;
        if (mode == 2) v += g_out[bi * OK + om];
        g_out[bi * OK + om] = v;
        float sq = v * v;
        sq += __shfl_xor_sync(0xffffffffu, sq, 1);
        sq += __shfl_xor_sync(0xffffffffu, sq, 2);
        sq += __shfl_xor_sync(0xffffffffu, sq, 4);
        float mg = sq + 1e-6f;
        actout[bi * OK + om] = v / mg * fmaxf(mg - 0.2f, 0.f);
    }
}

// ---------------- final projection + correction ----------------
__global__ void final_kernel(const float* __restrict__ p0,
                             const float* __restrict__ pc,
                             const float* __restrict__ pd,
                             float* __restrict__ outp) {
    int bi = blockIdx.x * blockDim.x + threadIdx.x;
    if (bi >= BN) return;
    float res[3][2] = {{0.f, 0.f}, {0.f, 0.f}, {0.f, 0.f}};
    float c0 = pc[0], c1 = pc[1], d0 = pd[0], d1 = pd[1];
#pragma unroll
    for (int m = 0; m < 8; ++m) {
        float th = (float)m * 0.78539816339744831f;
        float cs = cosf(th), sn = sinf(th);
        float Mc0 = c0 * cs - c1 * sn, Mc1 = c0 * sn + c1 * cs;
        float Md0 = d0 * cs - d1 * sn, Md1 = d0 * sn + d1 * cs;
#pragma unroll
        for (int ch = 0; ch < 3; ++ch) {
            float vc = g_oc[bi * 24 + ch * 8 + m];
            float vd = g_od[bi * 24 + ch * 8 + m];
            res[ch][0] += vc * Mc0 + vd * Md0;
            res[ch][1] += vc * Mc1 + vd * Md1;
        }
    }
    const float CORR = 1.0f / 128.0f;
    float pcx = g_p1[bi * 2 + 0] + CORR * res[0][0];
    float pcy = g_p1[bi * 2 + 1] + CORR * res[0][1];
    outp[bi * 2 + 0] = pcx;
    outp[bi * 2 + 1] = pcy;
    outp[BN * 2 + bi * 2 + 0] = pcx - p0[bi * 2 + 0];
    outp[BN * 2 + bi * 2 + 1] = pcy - p0[bi * 2 + 1];
    outp[BN * 4 + bi * 4 + 0] = CORR * res[1][0];
    outp[BN * 4 + bi * 4 + 1] = CORR * res[1][1];
    outp[BN * 4 + bi * 4 + 2] = CORR * res[2][0];
    outp[BN * 4 + bi * 4 + 3] = CORR * res[2][1];
}

// ---------------- launch ----------------
extern "C" void kernel_launch(void* const* d_in, const int* in_sizes, int n_in,
                              void* d_out, int out_size) {
    const float* p0_enc  = (const float*)d_in[0];
    const float* v0_enc  = (const float*)d_in[1];
    const float* p0      = (const float*)d_in[2];
    const float* v0      = (const float*)d_in[3];
    const float* a       = (const float*)d_in[4];
    const float* mask    = (const float*)d_in[5];
    const float* lift_c0 = (const float*)d_in[6];
    const float* Wc0     = (const float*)d_in[7];
    const float* lift_d0 = (const float*)d_in[8];
    const float* Wd0     = (const float*)d_in[9];
    const float* Wc1     = (const float*)d_in[10];
    const float* Wd1     = (const float*)d_in[11];
    const float* Wc2     = (const float*)d_in[12];
    const float* Wd2     = (const float*)d_in[13];
    const float* Wc3     = (const float*)d_in[14];
    const float* Wd3     = (const float*)d_in[15];
    const float* Wc4     = (const float*)d_in[16];
    const float* proj_c4 = (const float*)d_in[17];
    const float* Wd4     = (const float*)d_in[18];
    const float* proj_d4 = (const float*)d_in[19];

    const int NEXP = (1253376 + 26112 + 255) / 256;
    prep_kernel<<<BN + NEXP, 256>>>(mask, p0, v0, a, p0_enc, v0_enc,
                                    lift_c0, lift_d0,
                                    Wc0, Wc1, Wc2, Wc3, Wc4,
                                    Wd0, Wd1, Wd2, Wd3, Wd4);

    const int wOff[5] = {0, 196608, 393216, 786432, 1179648};
    const int dOff[5] = {0, 4096, 8192, 16384, 24576};

    // act ping-pong: L0 -> A; L1: A->B; L2: B->A; L3: A->B; L4: reads B
    // L0: CK=128, OK=32, KD=6144
    stage1_kernel<128><<<BN, 512>>>(0);
    gemm_kernel<32, 128, 2, 8, 16><<<dim3(8, 16), 256>>>(6144, wOff[0]);
    reduce_kernel<32, 8, 16, 128><<<BN / 8, 256>>>(0, dOff[0], 0, 1);
    // L1: CK=64, OK=64, KD=3072, residual
    stage1_kernel<64><<<BN, 512>>>(1);
    gemm_kernel<64, 64, 2, 8, 8><<<dim3(16, 8), 256>>>(3072, wOff[1]);
    reduce_kernel<64, 4, 8, 64><<<BN / 4, 256>>>(2, dOff[1], 1, 2);
    // L2: CK=64, OK=128, KD=3072
    stage1_kernel<64><<<BN, 512>>>(2);
    gemm_kernel<128, 32, 2, 8, 4><<<dim3(32, 4), 256>>>(3072, wOff[2]);
    reduce_kernel<128, 2, 4, 64><<<BN / 2, 256>>>(1, dOff[2], 2, 1);
    // L3: CK=128, OK=64, KD=6144
    stage1_kernel<128><<<BN, 512>>>(1);
    gemm_kernel<64, 64, 2, 8, 16><<<dim3(16, 16), 256>>>(6144, wOff[3]);
    reduce_kernel<64, 4, 16, 128><<<BN / 4, 256>>>(1, dOff[3], 1, 2);
    // L4: CK=64, OK=24, KD=3072, last
    stage1_kernel<64><<<BN, 512>>>(2);
    gemm_kernel<24, 128, 2, 8, 4><<<dim3(8, 4), 192>>>(3072, wOff[4]);
    reduce_kernel<24, 8, 4, 64><<<BN / 8, 192>>>(3, dOff[4], 2, 2);

    final_kernel<<<4, 256>>>(p0, proj_c4, proj_d4, (float*)d_out);
}

// round 13
// speedup vs baseline: 1.1042x; 1.0211x over previous
#include <cuda_runtime.h>

#define B_     2
#define NPART  512
#define BN     1024
#define GBINS  48
#define TWO_PI 6.283185307179586f
#define INV_2PI 0.15915494309189535f

// ---------------- static device scratch ----------------
__device__ float    g_p1[BN * 2];
__device__ float    g_regC[BN * 128];
__device__ float    g_regD[BN * 128];
__device__ float4   g_ent[BN * 1024];         // 2 entries/neighbor: (cr0, cr1, cr2, j)
__device__ int      g_binStart[BN * 17];      // CSR over 16 t-columns
__device__ float    g_F[BN * GBINS * 128];
__device__ float    g_out[BN * 128];
__device__ float    g_actA[BN * 128];
__device__ float    g_actB[BN * 128];
__device__ float    g_Wbig[1253376];
__device__ float    g_WdT[26112];
__device__ float    g_part[16 * BN * 64];     // split-K partials
__device__ float    g_oc[BN * 24];
__device__ float    g_od[BN * 24];

__constant__ int c_wOff[6] = {0, 196608, 393216, 786432, 1179648, 1253376};
__constant__ int c_dOff[6] = {0, 4096, 8192, 16384, 24576, 26112};

// ---------------- f32x2 helpers ----------------
__device__ __forceinline__ unsigned long long pack2(float x) {
    unsigned long long r;
    asm("mov.b64 %0, {%1, %1};" : "=l"(r) : "f"(x));
    return r;
}
__device__ __forceinline__ unsigned long long ffma2(unsigned long long a,
                                                    unsigned long long b,
                                                    unsigned long long c) {
    unsigned long long d;
    asm("fma.rn.f32x2 %0, %1, %2, %3;" : "=l"(d) : "l"(a), "l"(b), "l"(c));
    return d;
}
union F4U { float4 f4; float f[4]; unsigned long long u2[2]; };
union F2U { float2 f2; unsigned long long u2; };

// ---------------- prep: geom+lift (blocks 0..BN-1) and expand (rest) ----------------
__global__ void __launch_bounds__(256) prep_kernel(
        const float* __restrict__ mask, const float* __restrict__ p0,
        const float* __restrict__ v0, const float* __restrict__ a,
        const float* __restrict__ p0_enc, const float* __restrict__ v0_enc,
        const float* __restrict__ lc, const float* __restrict__ ld,
        const float* __restrict__ Wc0, const float* __restrict__ Wc1,
        const float* __restrict__ Wc2, const float* __restrict__ Wc3,
        const float* __restrict__ Wc4,
        const float* __restrict__ Wd0, const float* __restrict__ Wd1,
        const float* __restrict__ Wd2, const float* __restrict__ Wd3,
        const float* __restrict__ Wd4) {
    int tid = threadIdx.x;
    if (blockIdx.x >= BN) {
        const int Cs[5] = {16, 8, 8, 16, 8};
        const int Os[5] = {4, 8, 16, 8, 3};
        int idx = (blockIdx.x - BN) * 256 + tid;
        if (idx < 1253376) {
            int l = 0;
            while (idx >= c_wOff[l + 1]) ++l;
            int loc = idx - c_wOff[l];
            const float* Wc = (l == 0) ? Wc0 : (l == 1) ? Wc1 : (l == 2) ? Wc2 : (l == 3) ? Wc3 : Wc4;
            int C = Cs[l], OK = Os[l] * 8;
            int om = loc % OK;
            int kk = loc / OK;
            int n = kk & 7;
            int c = (kk >> 3) % C;
            int g = (kk >> 3) / C;
            int r = g >> 4, t = g & 15;
            int o = om >> 3, m = om & 7;
            g_Wbig[idx] = Wc[(((o * C + c) * 8 + ((n - m) & 7)) * 3 + r) * 16 + ((t - 2 * m) & 15)];
        } else if (idx < 1253376 + 26112) {
            int id2 = idx - 1253376;
            int l = 0;
            while (id2 >= c_dOff[l + 1]) ++l;
            int loc = id2 - c_dOff[l];
            const float* Wd = (l == 0) ? Wd0 : (l == 1) ? Wd1 : (l == 2) ? Wd2 : (l == 3) ? Wd3 : Wd4;
            int C = Cs[l], OK = Os[l] * 8;
            int om = loc % OK;
            int cn = loc / OK;
            int o = om >> 3, m = om & 7, c = cn >> 3, n = cn & 7;
            g_WdT[id2] = Wd[(o * C + c) * 8 + ((m - n) & 7)];
        }
        return;
    }

    __shared__ float sx[NPART], sy[NPART], smk[NPART], sw[NPART];
    __shared__ float red[256];
    __shared__ int cnt[16], offs[16], bstart[17];
    int bi = blockIdx.x;
    int b = bi >> 9, i = bi & 511;

    for (int j = tid; j < NPART; j += 256) {
        int gj = b * NPART + j;
        float vx = v0[gj * 2], vy = v0[gj * 2 + 1];
        sx[j] = p0[gj * 2 + 0] + vx + 0.5f * a[gj * 2 + 0];
        sy[j] = p0[gj * 2 + 1] + vy + 0.5f * a[gj * 2 + 1];
        smk[j] = mask[gj];
    }
    if (tid < 16) cnt[tid] = 0;

    if (tid < 128) {
        int c = tid >> 3, m = tid & 7;
        float v0x = v0[bi * 2 + 0], v0y = v0[bi * 2 + 1];
        float ax = a[bi * 2 + 0], ay = a[bi * 2 + 1];
        float v1x = v0x + ax, v1y = v0y + ay;
        float p1x = p0[bi * 2 + 0] + 0.5f * (v0x + v1x);
        float p1y = p0[bi * 2 + 1] + 0.5f * (v0y + v1y);
        float x, y;
        if (c == 0)      { x = v1x; y = v1y; }
        else if (c == 1) { x = p1x; y = p1y; }
        else if (c < 9)  { int t = c - 2; x = v0_enc[(bi * 7 + t) * 2 + 0]; y = v0_enc[(bi * 7 + t) * 2 + 1]; }
        else             { int t = c - 9; x = p0_enc[(bi * 7 + t) * 2 + 0]; y = p0_enc[(bi * 7 + t) * 2 + 1]; }
        float th = (float)m * 0.78539816339744831f;
        float cs = cosf(th), sn = sinf(th);
        float lc0 = lc[0], lc1 = lc[1], ld0 = ld[0], ld1 = ld[1];
        g_regC[bi * 128 + tid] = x * (lc0 * cs - lc1 * sn) + y * (lc0 * sn + lc1 * cs);
        g_regD[bi * 128 + tid] = x * (ld0 * cs - ld1 * sn) + y * (ld0 * sn + ld1 * cs);
    }
    __syncthreads();
    if (tid == 0) { g_p1[bi * 2] = sx[i]; g_p1[bi * 2 + 1] = sy[i]; }
    float xi = sx[i], yi = sy[i];

    float part = 0.f;
    for (int j = tid; j < NPART; j += 256) {
        float rx = sx[j] - xi, ry = sy[j] - yi;
        float d2 = (rx * rx + ry * ry + 1e-12f) * (0.025f * 0.025f);
        float u = fmaxf(1.f - d2, 0.f);
        float w = u * u * u * smk[j];
        sw[j] = w;
        part += w;
    }
    red[tid] = part;
    __syncthreads();
    for (int s = 128; s > 0; s >>= 1) { if (tid < s) red[tid] += red[tid + s]; __syncthreads(); }
    float inv = 1.f / (red[0] + 1e-6f);
    __syncthreads();

    float4 eloc[4];
    int tloc[4];
    int nloc = 0;
#pragma unroll
    for (int c = 0; c < 2; ++c) {
        int j = c * 256 + tid;
        float w = sw[j];
        if (w > 0.f) {
            float rx = sx[j] - xi, ry = sy[j] - yi;
            float d = sqrtf(rx * rx + ry * ry + 1e-12f) * 0.025f;
            float wb = w * inv;
            float rc = fminf(fmaxf(d * 3.f - 0.5f, 0.f), 2.f);
            float r0 = floorf(rc);
            float wr = rc - r0;
            int r0i = (int)r0;
            float w0 = wb * (1.f - wr), w1 = wb * wr;
            float b0, b1, b2;
            if (r0i == 0)      { b0 = w0; b1 = w1; b2 = 0.f; }
            else if (r0i == 1) { b0 = 0.f; b1 = w0; b2 = w1; }
            else               { b0 = 0.f; b1 = 0.f; b2 = w0 + w1; }
            float axv = (j == i) ? 1.f : rx;
            float ayv = (j == i) ? 0.f : ry;
            float ang = atan2f(ayv, axv);
            ang = ang - TWO_PI * floorf(ang * INV_2PI);
            float tc = ang * (16.f * INV_2PI);
            float t0 = floorf(tc);
            float wt = tc - t0;
            int t0i = ((int)t0) & 15;
            int t1i = (t0i + 1) & 15;
            float jf = __int_as_float(j);
            float u0 = 1.f - wt;
            eloc[nloc] = make_float4(b0 * u0, b1 * u0, b2 * u0, jf);
            tloc[nloc] = t0i;
            ++nloc;
            atomicAdd(&cnt[t0i], 1);
            eloc[nloc] = make_float4(b0 * wt, b1 * wt, b2 * wt, jf);
            tloc[nloc] = t1i;
            ++nloc;
            atomicAdd(&cnt[t1i], 1);
        }
    }
    __syncthreads();
    if (tid == 0) {
        int s = 0;
        for (int g = 0; g < 16; ++g) { bstart[g] = s; s += cnt[g]; }
        bstart[16] = s;
    }
    __syncthreads();
    if (tid < 16) offs[tid] = bstart[tid];
    if (tid < 17) g_binStart[bi * 17 + tid] = bstart[tid];
    __syncthreads();

    float4* ent = g_ent + (size_t)bi * 1024;
    for (int l = 0; l < nloc; ++l) {
        int pos = atomicAdd(&offs[tloc[l]], 1);
        ent[pos] = eloc[l];
    }
}

// ---------------- stage 1: single-list t-column gather, unroll-2 ----------------
template <int CK>
__global__ void __launch_bounds__(512) stage1_kernel(int srcsel) {
    const int V2 = CK / 64;
    int bi = blockIdx.x;
    int b = bi >> 9;
    int tid = threadIdx.x;
    int warp = tid >> 5, lane = tid & 31;
    const float* __restrict__ feats = (srcsel == 0) ? g_regC : (srcsel == 1) ? g_actA : g_actB;

    __shared__ int bs[17];
    if (tid < 17) bs[tid] = g_binStart[bi * 17 + tid];
    __syncthreads();

    const float4* __restrict__ ent = g_ent + (size_t)bi * 1024;
    const float* __restrict__ fb = feats + (size_t)b * NPART * CK;

    unsigned long long a0[V2], a1[V2], a2[V2];
#pragma unroll
    for (int v = 0; v < V2; ++v) { a0[v] = 0ull; a1[v] = 0ull; a2[v] = 0ull; }

    int s = bs[warp], e = bs[warp + 1];
    int k = s;
    for (; k + 2 <= e; k += 2) {
        float4 m0 = ent[k], m1 = ent[k + 1];
        int j0 = __float_as_int(m0.w), j1 = __float_as_int(m1.w);
        if (V2 == 2) {
            F4U f0, f1;
            f0.f4 = *(const float4*)(fb + j0 * CK + lane * 4);
            f1.f4 = *(const float4*)(fb + j1 * CK + lane * 4);
            unsigned long long p00 = pack2(m0.x), p01 = pack2(m0.y), p02 = pack2(m0.z);
            unsigned long long p10 = pack2(m1.x), p11 = pack2(m1.y), p12 = pack2(m1.z);
            a0[0] = ffma2(p00, f0.u2[0], a0[0]);
            a0[1] = ffma2(p00, f0.u2[1], a0[1]);
            a1[0] = ffma2(p01, f0.u2[0], a1[0]);
            a1[1] = ffma2(p01, f0.u2[1], a1[1]);
            a2[0] = ffma2(p02, f0.u2[0], a2[0]);
            a2[1] = ffma2(p02, f0.u2[1], a2[1]);
            a0[0] = ffma2(p10, f1.u2[0], a0[0]);
            a0[1] = ffma2(p10, f1.u2[1], a0[1]);
            a1[0] = ffma2(p11, f1.u2[0], a1[0]);
            a1[1] = ffma2(p11, f1.u2[1], a1[1]);
            a2[0] = ffma2(p12, f1.u2[0], a2[0]);
            a2[1] = ffma2(p12, f1.u2[1], a2[1]);
        } else {
            F2U f0, f1;
            f0.f2 = *(const float2*)(fb + j0 * CK + lane * 2);
            f1.f2 = *(const float2*)(fb + j1 * CK + lane * 2);
            a0[0] = ffma2(pack2(m0.x), f0.u2, a0[0]);
            a1[0] = ffma2(pack2(m0.y), f0.u2, a1[0]);
            a2[0] = ffma2(pack2(m0.z), f0.u2, a2[0]);
            a0[0] = ffma2(pack2(m1.x), f1.u2, a0[0]);
            a1[0] = ffma2(pack2(m1.y), f1.u2, a1[0]);
            a2[0] = ffma2(pack2(m1.z), f1.u2, a2[0]);
        }
    }
    if (k < e) {
        float4 m = ent[k];
        int j = __float_as_int(m.w);
        if (V2 == 2) {
            F4U f;
            f.f4 = *(const float4*)(fb + j * CK + lane * 4);
            unsigned long long p0 = pack2(m.x), p1 = pack2(m.y), p2 = pack2(m.z);
            a0[0] = ffma2(p0, f.u2[0], a0[0]);
            a0[1] = ffma2(p0, f.u2[1], a0[1]);
            a1[0] = ffma2(p1, f.u2[0], a1[0]);
            a1[1] = ffma2(p1, f.u2[1], a1[1]);
            a2[0] = ffma2(p2, f.u2[0], a2[0]);
            a2[1] = ffma2(p2, f.u2[1], a2[1]);
        } else {
            F2U f;
            f.f2 = *(const float2*)(fb + j * CK + lane * 2);
            a0[0] = ffma2(pack2(m.x), f.u2, a0[0]);
            a1[0] = ffma2(pack2(m.y), f.u2, a1[0]);
            a2[0] = ffma2(pack2(m.z), f.u2, a2[0]);
        }
    }

    float* Fb = g_F + (size_t)bi * GBINS * CK;
    if (V2 == 2) {
        F4U o0, o1, o2;
        o0.u2[0] = a0[0]; o0.u2[1] = a0[1];
        o1.u2[0] = a1[0]; o1.u2[1] = a1[1];
        o2.u2[0] = a2[0]; o2.u2[1] = a2[1];
        *(float4*)(Fb + (0 * 16 + warp) * CK + lane * 4) = o0.f4;
        *(float4*)(Fb + (1 * 16 + warp) * CK + lane * 4) = o1.f4;
        *(float4*)(Fb + (2 * 16 + warp) * CK + lane * 4) = o2.f4;
    } else {
        F2U o0, o1, o2;
        o0.u2 = a0[0]; o1.u2 = a1[0]; o2.u2 = a2[0];
        *(float2*)(Fb + (0 * 16 + warp) * CK + lane * 2) = o0.f2;
        *(float2*)(Fb + (1 * 16 + warp) * CK + lane * 2) = o1.f2;
        *(float2*)(Fb + (2 * 16 + warp) * CK + lane * 2) = o2.f2;
    }
}

// ---------------- stage 2a: split-K GEMM (partials only) ----------------
template <int OK, int TM, int ROWS, int CPT, int KS>
__global__ void __launch_bounds__((TM / ROWS) * (OK / CPT)) gemm_kernel(int KD, int wOff) {
    const int KB = 32;
    const int THREADS = (TM / ROWS) * (OK / CPT);
    const int NW4 = (KB * OK / 4 + THREADS - 1) / THREADS;
    const int NF4 = (TM * KB / 4 + THREADS - 1) / THREADS;
    __shared__ __align__(16) float Wt[KB * OK];
    __shared__ __align__(16) float Ft[TM * KB];
    int tid = threadIdx.x;
    int i0 = blockIdx.x * TM;
    int KC = KD / KS;
    int k0 = blockIdx.y * KC;
    int NCH = KC / KB;

    const float* Wsrc = g_Wbig + wOff + (size_t)k0 * OK;

    float4 wreg[NW4], freg[NF4];
    {
        const float4* src = (const float4*)Wsrc;
#pragma unroll
        for (int u = 0; u < NW4; ++u) {
            int x = tid + u * THREADS;
            if (x < KB * OK / 4) wreg[u] = src[x];
        }
#pragma unroll
        for (int u = 0; u < NF4; ++u) {
            int x = tid + u * THREADS;
            if (x < TM * KB / 4) {
                int row = x / (KB / 4), kc = x % (KB / 4);
                freg[u] = *(const float4*)(g_F + (size_t)(i0 + row) * KD + k0 + kc * 4);
            }
        }
    }

    int rg = tid / (OK / CPT);
    int cg = (tid % (OK / CPT)) * CPT;
    unsigned long long accp[ROWS][CPT / 2];
#pragma unroll
    for (int r = 0; r < ROWS; ++r)
#pragma unroll
        for (int c = 0; c < CPT / 2; ++c) accp[r][c] = 0ull;

    for (int ch = 0; ch < NCH; ++ch) {
        __syncthreads();
#pragma unroll
        for (int u = 0; u < NW4; ++u) {
            int x = tid + u * THREADS;
            if (x < KB * OK / 4) ((float4*)Wt)[x] = wreg[u];
        }
#pragma unroll
        for (int u = 0; u < NF4; ++u) {
            int x = tid + u * THREADS;
            if (x < TM * KB / 4) ((float4*)Ft)[x] = freg[u];
        }
        __syncthreads();
        if (ch + 1 < NCH) {
            const float4* src = (const float4*)(Wsrc + (size_t)(ch + 1) * KB * OK);
#pragma unroll
            for (int u = 0; u < NW4; ++u) {
                int x = tid + u * THREADS;
                if (x < KB * OK / 4) wreg[u] = src[x];
            }
#pragma unroll
            for (int u = 0; u < NF4; ++u) {
                int x = tid + u * THREADS;
                if (x < TM * KB / 4) {
                    int rr = x / (KB / 4), kc = x % (KB / 4);
                    freg[u] = *(const float4*)(g_F + (size_t)(i0 + rr) * KD + k0 + (ch + 1) * KB + kc * 4);
                }
            }
        }
#pragma unroll 4
        for (int k = 0; k < KB; ++k) {
            unsigned long long fp[ROWS];
#pragma unroll
            for (int r = 0; r < ROWS; ++r)
                fp[r] = pack2(Ft[(rg * ROWS + r) * KB + k]);
#pragma unroll
            for (int c = 0; c < CPT; c += 4) {
                F4U w;
                w.f4 = *(const float4*)&Wt[k * OK + cg + c];
#pragma unroll
                for (int r = 0; r < ROWS; ++r) {
                    accp[r][c / 2]     = ffma2(fp[r], w.u2[0], accp[r][c / 2]);
                    accp[r][c / 2 + 1] = ffma2(fp[r], w.u2[1], accp[r][c / 2 + 1]);
                }
            }
        }
    }

#pragma unroll
    for (int r = 0; r < ROWS; ++r) {
        float* dst = g_part + ((size_t)blockIdx.y * BN + i0 + rg * ROWS + r) * OK + cg;
#pragma unroll
        for (int c = 0; c < CPT; c += 4) {
            F4U o;
            o.u2[0] = accp[r][c / 2];
            o.u2[1] = accp[r][c / 2 + 1];
            *(float4*)&dst[c] = o.f4;
        }
    }
}

// ---------------- stage 2b: deterministic reduce + dense + epilogue ----------------
template <int OK, int ROWS, int KS, int CK>
__global__ void __launch_bounds__(OK * ROWS) reduce_kernel(int mode, int dOff,
                                                           int ain, int aout) {
    int tid = threadIdx.x;
    int row = tid / OK, om = tid % OK;
    int bi = blockIdx.x * ROWS + row;

    float oc = 0.f;
#pragma unroll
    for (int ks = 0; ks < KS; ++ks)
        oc += g_part[((size_t)ks * BN + bi) * OK + om];

    const float* __restrict__ densein = (ain == 0) ? g_regD : (ain == 1) ? g_actA : g_actB;
    float* __restrict__ actout = (aout == 1) ? g_actA : g_actB;
    const float* WdT = g_WdT + dOff;
    const float* x = densein + (size_t)bi * CK;
    float od = 0.f;
#pragma unroll 16
    for (int cn = 0; cn < CK; ++cn) od = fmaf(x[cn], WdT[cn * OK + om], od);

    if (mode == 0) {
        g_out[bi * 64 + om] = oc;
        g_out[bi * 64 + 32 + om] = od;
        float sc = oc * oc;
        sc += __shfl_xor_sync(0xffffffffu, sc, 1);
        sc += __shfl_xor_sync(0xffffffffu, sc, 2);
        sc += __shfl_xor_sync(0xffffffffu, sc, 4);
        float mc = sc + 1e-6f;
        actout[bi * 64 + om] = oc / mc * fmaxf(mc - 0.2f, 0.f);
        float sd = od * od;
        sd += __shfl_xor_sync(0xffffffffu, sd, 1);
        sd += __shfl_xor_sync(0xffffffffu, sd, 2);
        sd += __shfl_xor_sync(0xffffffffu, sd, 4);
        float md = sd + 1e-6f;
        actout[bi * 64 + 32 + om] = od / md * fmaxf(md - 0.2f, 0.f);
    } else {
        float v = oc + od;
        if (mode == 2) v += g_out[bi * OK + om];
        g_out[bi * OK + om] = v;
        float sq = v * v;
        sq += __shfl_xor_sync(0xffffffffu, sq, 1);
        sq += __shfl_xor_sync(0xffffffffu, sq, 2);
        sq += __shfl_xor_sync(0xffffffffu, sq, 4);
        float mg = sq + 1e-6f;
        actout[bi * OK + om] = v / mg * fmaxf(mg - 0.2f, 0.f);
    }
}

// ---------------- last layer: reduce + dense + projection, fused ----------------
// OK=24 conv cols; dense dot 24 outputs; projection in-block.
__global__ void __launch_bounds__(96) reduce_last(const float* __restrict__ p0,
                                                  const float* __restrict__ pc,
                                                  const float* __restrict__ pd,
                                                  float* __restrict__ outp) {
    const int OK = 24, ROWS = 4, KS = 4, CK = 64;
    __shared__ float soc[ROWS][OK], sod[ROWS][OK];
    int tid = threadIdx.x;
    int row = tid / OK, om = tid % OK;
    int bi = blockIdx.x * ROWS + row;

    float oc = 0.f;
#pragma unroll
    for (int ks = 0; ks < KS; ++ks)
        oc += g_part[((size_t)ks * BN + bi) * OK + om];

    const float* WdT = g_WdT + 24576;
    const float* x = g_actB + (size_t)bi * CK;
    float od = 0.f;
#pragma unroll 16
    for (int cn = 0; cn < CK; ++cn) od = fmaf(x[cn], WdT[cn * OK + om], od);

    soc[row][om] = oc;
    sod[row][om] = od;
    __syncthreads();

    if (om < 6) {
        int ch = om >> 1, xy = om & 1;
        float c0 = pc[0], c1 = pc[1], d0 = pd[0], d1 = pd[1];
        float res = 0.f;
#pragma unroll
        for (int m = 0; m < 8; ++m) {
            float th = (float)m * 0.78539816339744831f;
            float cs = cosf(th), sn = sinf(th);
            float Mc = (xy == 0) ? (c0 * cs - c1 * sn) : (c0 * sn + c1 * cs);
            float Md = (xy == 0) ? (d0 * cs - d1 * sn) : (d0 * sn + d1 * cs);
            res += soc[row][ch * 8 + m] * Mc + sod[row][ch * 8 + m] * Md;
        }
        res *= (1.0f / 128.0f);
        if (ch == 0) {
            float pcv = g_p1[bi * 2 + xy] + res;
            outp[bi * 2 + xy] = pcv;
            outp[BN * 2 + bi * 2 + xy] = pcv - p0[bi * 2 + xy];
        } else {
            outp[BN * 4 + bi * 4 + (ch - 1) * 2 + xy] = res;
        }
    }
}

// ---------------- launch ----------------
extern "C" void kernel_launch(void* const* d_in, const int* in_sizes, int n_in,
                              void* d_out, int out_size) {
    const float* p0_enc  = (const float*)d_in[0];
    const float* v0_enc  = (const float*)d_in[1];
    const float* p0      = (const float*)d_in[2];
    const float* v0      = (const float*)d_in[3];
    const float* a       = (const float*)d_in[4];
    const float* mask    = (const float*)d_in[5];
    const float* lift_c0 = (const float*)d_in[6];
    const float* Wc0     = (const float*)d_in[7];
    const float* lift_d0 = (const float*)d_in[8];
    const float* Wd0     = (const float*)d_in[9];
    const float* Wc1     = (const float*)d_in[10];
    const float* Wd1     = (const float*)d_in[11];
    const float* Wc2     = (const float*)d_in[12];
    const float* Wd2     = (const float*)d_in[13];
    const float* Wc3     = (const float*)d_in[14];
    const float* Wd3     = (const float*)d_in[15];
    const float* Wc4     = (const float*)d_in[16];
    const float* proj_c4 = (const float*)d_in[17];
    const float* Wd4     = (const float*)d_in[18];
    const float* proj_d4 = (const float*)d_in[19];

    const int NEXP = (1253376 + 26112 + 255) / 256;
    prep_kernel<<<BN + NEXP, 256>>>(mask, p0, v0, a, p0_enc, v0_enc,
                                    lift_c0, lift_d0,
                                    Wc0, Wc1, Wc2, Wc3, Wc4,
                                    Wd0, Wd1, Wd2, Wd3, Wd4);

    const int wOff[5] = {0, 196608, 393216, 786432, 1179648};
    const int dOff[5] = {0, 4096, 8192, 16384, 24576};

    // act ping-pong: L0 -> A; L1: A->B; L2: B->A; L3: A->B; L4: reads B
    // L0: CK=128, OK=32, KD=6144
    stage1_kernel<128><<<BN, 512>>>(0);
    gemm_kernel<32, 128, 2, 8, 16><<<dim3(8, 16), 256>>>(6144, wOff[0]);
    reduce_kernel<32, 4, 16, 128><<<BN / 4, 128>>>(0, dOff[0], 0, 1);
    // L1: CK=64, OK=64, KD=3072, residual
    stage1_kernel<64><<<BN, 512>>>(1);
    gemm_kernel<64, 64, 2, 8, 8><<<dim3(16, 8), 256>>>(3072, wOff[1]);
    reduce_kernel<64, 2, 8, 64><<<BN / 2, 128>>>(2, dOff[1], 1, 2);
    // L2: CK=64, OK=128, KD=3072
    stage1_kernel<64><<<BN, 512>>>(2);
    gemm_kernel<128, 32, 2, 8, 4><<<dim3(32, 4), 256>>>(3072, wOff[2]);
    reduce_kernel<128, 1, 4, 64><<<BN, 128>>>(1, dOff[2], 2, 1);
    // L3: CK=128, OK=64, KD=6144
    stage1_kernel<128><<<BN, 512>>>(1);
    gemm_kernel<64, 64, 2, 8, 16><<<dim3(16, 16), 256>>>(6144, wOff[3]);
    reduce_kernel<64, 2, 16, 128><<<BN / 2, 128>>>(1, dOff[3], 1, 2);
    // L4: CK=64, OK=24, KD=3072, last (fused projection)
    stage1_kernel<64><<<BN, 512>>>(2);
    gemm_kernel<24, 128, 2, 8, 4><<<dim3(8, 4), 192>>>(3072, wOff[4]);
    reduce_last<<<BN / 4, 96>>>(p0, proj_c4, proj_d4, (float*)d_out);
}

// round 14
// speedup vs baseline: 1.1393x; 1.0318x over previous
#include <cuda_runtime.h>

#define B_     2
#define NPART  512
#define BN     1024
#define GBINS  48
#define TWO_PI 6.283185307179586f
#define INV_2PI 0.15915494309189535f

// ---------------- static device scratch ----------------
__device__ float    g_p1[BN * 2];
__device__ float    g_regC[BN * 128];
__device__ float    g_regD[BN * 128];
__device__ float4   g_ent[BN * 1024];         // 2 entries/neighbor: (cr0, cr1, cr2, j)
__device__ int      g_binStart[BN * 17];      // CSR over 16 t-columns
__device__ float    g_F[BN * GBINS * 128];
__device__ float    g_out[BN * 128];
__device__ float    g_actA[BN * 128];
__device__ float    g_actB[BN * 128];
__device__ float    g_Wbig[1253376];
__device__ float    g_WdT[26112];
__device__ float    g_part[16 * BN * 64];     // split-K partials (1M floats)
__constant__ int c_wOff[6] = {0, 196608, 393216, 786432, 1179648, 1253376};
__constant__ int c_dOff[6] = {0, 4096, 8192, 16384, 24576, 26112};

// ---------------- f32x2 helpers ----------------
__device__ __forceinline__ unsigned long long pack2(float x) {
    unsigned long long r;
    asm("mov.b64 %0, {%1, %1};" : "=l"(r) : "f"(x));
    return r;
}
__device__ __forceinline__ unsigned long long ffma2(unsigned long long a,
                                                    unsigned long long b,
                                                    unsigned long long c) {
    unsigned long long d;
    asm("fma.rn.f32x2 %0, %1, %2, %3;" : "=l"(d) : "l"(a), "l"(b), "l"(c));
    return d;
}
union F4U { float4 f4; float f[4]; unsigned long long u2[2]; };
union F2U { float2 f2; unsigned long long u2; };

// ---------------- prep: geom+lift (blocks 0..BN-1) and expand (rest) ----------------
__global__ void __launch_bounds__(256) prep_kernel(
        const float* __restrict__ mask, const float* __restrict__ p0,
        const float* __restrict__ v0, const float* __restrict__ a,
        const float* __restrict__ p0_enc, const float* __restrict__ v0_enc,
        const float* __restrict__ lc, const float* __restrict__ ld,
        const float* __restrict__ Wc0, const float* __restrict__ Wc1,
        const float* __restrict__ Wc2, const float* __restrict__ Wc3,
        const float* __restrict__ Wc4,
        const float* __restrict__ Wd0, const float* __restrict__ Wd1,
        const float* __restrict__ Wd2, const float* __restrict__ Wd3,
        const float* __restrict__ Wd4) {
    int tid = threadIdx.x;
    if (blockIdx.x >= BN) {
        const int Cs[5] = {16, 8, 8, 16, 8};
        const int Os[5] = {4, 8, 16, 8, 3};
        int idx = (blockIdx.x - BN) * 256 + tid;
        if (idx < 1253376) {
            int l = 0;
            while (idx >= c_wOff[l + 1]) ++l;
            int loc = idx - c_wOff[l];
            const float* Wc = (l == 0) ? Wc0 : (l == 1) ? Wc1 : (l == 2) ? Wc2 : (l == 3) ? Wc3 : Wc4;
            int C = Cs[l], OK = Os[l] * 8;
            int om = loc % OK;
            int kk = loc / OK;
            int n = kk & 7;
            int c = (kk >> 3) % C;
            int g = (kk >> 3) / C;
            int r = g >> 4, t = g & 15;
            int o = om >> 3, m = om & 7;
            g_Wbig[idx] = Wc[(((o * C + c) * 8 + ((n - m) & 7)) * 3 + r) * 16 + ((t - 2 * m) & 15)];
        } else if (idx < 1253376 + 26112) {
            int id2 = idx - 1253376;
            int l = 0;
            while (id2 >= c_dOff[l + 1]) ++l;
            int loc = id2 - c_dOff[l];
            const float* Wd = (l == 0) ? Wd0 : (l == 1) ? Wd1 : (l == 2) ? Wd2 : (l == 3) ? Wd3 : Wd4;
            int C = Cs[l], OK = Os[l] * 8;
            int om = loc % OK;
            int cn = loc / OK;
            int o = om >> 3, m = om & 7, c = cn >> 3, n = cn & 7;
            g_WdT[id2] = Wd[(o * C + c) * 8 + ((m - n) & 7)];
        }
        return;
    }

    __shared__ float sx[NPART], sy[NPART], smk[NPART], sw[NPART];
    __shared__ float red[256];
    __shared__ int cnt[16], offs[16], bstart[17];
    int bi = blockIdx.x;
    int b = bi >> 9, i = bi & 511;

    for (int j = tid; j < NPART; j += 256) {
        int gj = b * NPART + j;
        float vx = v0[gj * 2], vy = v0[gj * 2 + 1];
        sx[j] = p0[gj * 2 + 0] + vx + 0.5f * a[gj * 2 + 0];
        sy[j] = p0[gj * 2 + 1] + vy + 0.5f * a[gj * 2 + 1];
        smk[j] = mask[gj];
    }
    if (tid < 16) cnt[tid] = 0;

    if (tid < 128) {
        int c = tid >> 3, m = tid & 7;
        float v0x = v0[bi * 2 + 0], v0y = v0[bi * 2 + 1];
        float ax = a[bi * 2 + 0], ay = a[bi * 2 + 1];
        float v1x = v0x + ax, v1y = v0y + ay;
        float p1x = p0[bi * 2 + 0] + 0.5f * (v0x + v1x);
        float p1y = p0[bi * 2 + 1] + 0.5f * (v0y + v1y);
        float x, y;
        if (c == 0)      { x = v1x; y = v1y; }
        else if (c == 1) { x = p1x; y = p1y; }
        else if (c < 9)  { int t = c - 2; x = v0_enc[(bi * 7 + t) * 2 + 0]; y = v0_enc[(bi * 7 + t) * 2 + 1]; }
        else             { int t = c - 9; x = p0_enc[(bi * 7 + t) * 2 + 0]; y = p0_enc[(bi * 7 + t) * 2 + 1]; }
        float th = (float)m * 0.78539816339744831f;
        float cs = cosf(th), sn = sinf(th);
        float lc0 = lc[0], lc1 = lc[1], ld0 = ld[0], ld1 = ld[1];
        g_regC[bi * 128 + tid] = x * (lc0 * cs - lc1 * sn) + y * (lc0 * sn + lc1 * cs);
        g_regD[bi * 128 + tid] = x * (ld0 * cs - ld1 * sn) + y * (ld0 * sn + ld1 * cs);
    }
    __syncthreads();
    if (tid == 0) { g_p1[bi * 2] = sx[i]; g_p1[bi * 2 + 1] = sy[i]; }
    float xi = sx[i], yi = sy[i];

    float part = 0.f;
    for (int j = tid; j < NPART; j += 256) {
        float rx = sx[j] - xi, ry = sy[j] - yi;
        float d2 = (rx * rx + ry * ry + 1e-12f) * (0.025f * 0.025f);
        float u = fmaxf(1.f - d2, 0.f);
        float w = u * u * u * smk[j];
        sw[j] = w;
        part += w;
    }
    red[tid] = part;
    __syncthreads();
    for (int s = 128; s > 0; s >>= 1) { if (tid < s) red[tid] += red[tid + s]; __syncthreads(); }
    float inv = 1.f / (red[0] + 1e-6f);
    __syncthreads();

    float4 eloc[4];
    int tloc[4];
    int nloc = 0;
#pragma unroll
    for (int c = 0; c < 2; ++c) {
        int j = c * 256 + tid;
        float w = sw[j];
        if (w > 0.f) {
            float rx = sx[j] - xi, ry = sy[j] - yi;
            float d = sqrtf(rx * rx + ry * ry + 1e-12f) * 0.025f;
            float wb = w * inv;
            float rc = fminf(fmaxf(d * 3.f - 0.5f, 0.f), 2.f);
            float r0 = floorf(rc);
            float wr = rc - r0;
            int r0i = (int)r0;
            float w0 = wb * (1.f - wr), w1 = wb * wr;
            float b0, b1, b2;
            if (r0i == 0)      { b0 = w0; b1 = w1; b2 = 0.f; }
            else if (r0i == 1) { b0 = 0.f; b1 = w0; b2 = w1; }
            else               { b0 = 0.f; b1 = 0.f; b2 = w0 + w1; }
            float axv = (j == i) ? 1.f : rx;
            float ayv = (j == i) ? 0.f : ry;
            float ang = atan2f(ayv, axv);
            ang = ang - TWO_PI * floorf(ang * INV_2PI);
            float tc = ang * (16.f * INV_2PI);
            float t0 = floorf(tc);
            float wt = tc - t0;
            int t0i = ((int)t0) & 15;
            int t1i = (t0i + 1) & 15;
            float jf = __int_as_float(j);
            float u0 = 1.f - wt;
            eloc[nloc] = make_float4(b0 * u0, b1 * u0, b2 * u0, jf);
            tloc[nloc] = t0i;
            ++nloc;
            atomicAdd(&cnt[t0i], 1);
            eloc[nloc] = make_float4(b0 * wt, b1 * wt, b2 * wt, jf);
            tloc[nloc] = t1i;
            ++nloc;
            atomicAdd(&cnt[t1i], 1);
        }
    }
    __syncthreads();
    if (tid == 0) {
        int s = 0;
        for (int g = 0; g < 16; ++g) { bstart[g] = s; s += cnt[g]; }
        bstart[16] = s;
    }
    __syncthreads();
    if (tid < 16) offs[tid] = bstart[tid];
    if (tid < 17) g_binStart[bi * 17 + tid] = bstart[tid];
    __syncthreads();

    float4* ent = g_ent + (size_t)bi * 1024;
    for (int l = 0; l < nloc; ++l) {
        int pos = atomicAdd(&offs[tloc[l]], 1);
        ent[pos] = eloc[l];
    }
}

// ---------------- stage 1: single-list t-column gather ----------------
template <int CK>
__global__ void __launch_bounds__(512) stage1_kernel(int srcsel) {
    const int V2 = CK / 64;
    int bi = blockIdx.x;
    int b = bi >> 9;
    int tid = threadIdx.x;
    int warp = tid >> 5, lane = tid & 31;
    const float* __restrict__ feats = (srcsel == 0) ? g_regC : (srcsel == 1) ? g_actA : g_actB;

    __shared__ int bs[17];
    if (tid < 17) bs[tid] = g_binStart[bi * 17 + tid];
    __syncthreads();

    const float4* __restrict__ ent = g_ent + (size_t)bi * 1024;
    const float* __restrict__ fb = feats + (size_t)b * NPART * CK;

    unsigned long long a0[V2], a1[V2], a2[V2];
#pragma unroll
    for (int v = 0; v < V2; ++v) { a0[v] = 0ull; a1[v] = 0ull; a2[v] = 0ull; }

    int s = bs[warp], e = bs[warp + 1];
    int k = s;
    if (V2 == 2) {
        for (; k + 2 <= e; k += 2) {
            float4 m0 = ent[k], m1 = ent[k + 1];
            int j0 = __float_as_int(m0.w), j1 = __float_as_int(m1.w);
            F4U f0, f1;
            f0.f4 = *(const float4*)(fb + j0 * CK + lane * 4);
            f1.f4 = *(const float4*)(fb + j1 * CK + lane * 4);
            unsigned long long p00 = pack2(m0.x), p01 = pack2(m0.y), p02 = pack2(m0.z);
            unsigned long long p10 = pack2(m1.x), p11 = pack2(m1.y), p12 = pack2(m1.z);
            a0[0] = ffma2(p00, f0.u2[0], a0[0]);
            a0[1] = ffma2(p00, f0.u2[1], a0[1]);
            a1[0] = ffma2(p01, f0.u2[0], a1[0]);
            a1[1] = ffma2(p01, f0.u2[1], a1[1]);
            a2[0] = ffma2(p02, f0.u2[0], a2[0]);
            a2[1] = ffma2(p02, f0.u2[1], a2[1]);
            a0[0] = ffma2(p10, f1.u2[0], a0[0]);
            a0[1] = ffma2(p10, f1.u2[1], a0[1]);
            a1[0] = ffma2(p11, f1.u2[0], a1[0]);
            a1[1] = ffma2(p11, f1.u2[1], a1[1]);
            a2[0] = ffma2(p12, f1.u2[0], a2[0]);
            a2[1] = ffma2(p12, f1.u2[1], a2[1]);
        }
        for (; k < e; ++k) {
            float4 m = ent[k];
            int j = __float_as_int(m.w);
            F4U f;
            f.f4 = *(const float4*)(fb + j * CK + lane * 4);
            unsigned long long p0 = pack2(m.x), p1 = pack2(m.y), p2 = pack2(m.z);
            a0[0] = ffma2(p0, f.u2[0], a0[0]);
            a0[1] = ffma2(p0, f.u2[1], a0[1]);
            a1[0] = ffma2(p1, f.u2[0], a1[0]);
            a1[1] = ffma2(p1, f.u2[1], a1[1]);
            a2[0] = ffma2(p2, f.u2[0], a2[0]);
            a2[1] = ffma2(p2, f.u2[1], a2[1]);
        }
    } else {
        for (; k + 4 <= e; k += 4) {
            float4 m0 = ent[k], m1 = ent[k + 1], m2 = ent[k + 2], m3 = ent[k + 3];
            F2U f0, f1, f2, f3;
            f0.f2 = *(const float2*)(fb + __float_as_int(m0.w) * CK + lane * 2);
            f1.f2 = *(const float2*)(fb + __float_as_int(m1.w) * CK + lane * 2);
            f2.f2 = *(const float2*)(fb + __float_as_int(m2.w) * CK + lane * 2);
            f3.f2 = *(const float2*)(fb + __float_as_int(m3.w) * CK + lane * 2);
            a0[0] = ffma2(pack2(m0.x), f0.u2, a0[0]);
            a1[0] = ffma2(pack2(m0.y), f0.u2, a1[0]);
            a2[0] = ffma2(pack2(m0.z), f0.u2, a2[0]);
            a0[0] = ffma2(pack2(m1.x), f1.u2, a0[0]);
            a1[0] = ffma2(pack2(m1.y), f1.u2, a1[0]);
            a2[0] = ffma2(pack2(m1.z), f1.u2, a2[0]);
            a0[0] = ffma2(pack2(m2.x), f2.u2, a0[0]);
            a1[0] = ffma2(pack2(m2.y), f2.u2, a1[0]);
            a2[0] = ffma2(pack2(m2.z), f2.u2, a2[0]);
            a0[0] = ffma2(pack2(m3.x), f3.u2, a0[0]);
            a1[0] = ffma2(pack2(m3.y), f3.u2, a1[0]);
            a2[0] = ffma2(pack2(m3.z), f3.u2, a2[0]);
        }
        for (; k < e; ++k) {
            float4 m = ent[k];
            F2U f;
            f.f2 = *(const float2*)(fb + __float_as_int(m.w) * CK + lane * 2);
            a0[0] = ffma2(pack2(m.x), f.u2, a0[0]);
            a1[0] = ffma2(pack2(m.y), f.u2, a1[0]);
            a2[0] = ffma2(pack2(m.z), f.u2, a2[0]);
        }
    }

    float* Fb = g_F + (size_t)bi * GBINS * CK;
    if (V2 == 2) {
        F4U o0, o1, o2;
        o0.u2[0] = a0[0]; o0.u2[1] = a0[1];
        o1.u2[0] = a1[0]; o1.u2[1] = a1[1];
        o2.u2[0] = a2[0]; o2.u2[1] = a2[1];
        *(float4*)(Fb + (0 * 16 + warp) * CK + lane * 4) = o0.f4;
        *(float4*)(Fb + (1 * 16 + warp) * CK + lane * 4) = o1.f4;
        *(float4*)(Fb + (2 * 16 + warp) * CK + lane * 4) = o2.f4;
    } else {
        F2U o0, o1, o2;
        o0.u2 = a0[0]; o1.u2 = a1[0]; o2.u2 = a2[0];
        *(float2*)(Fb + (0 * 16 + warp) * CK + lane * 2) = o0.f2;
        *(float2*)(Fb + (1 * 16 + warp) * CK + lane * 2) = o1.f2;
        *(float2*)(Fb + (2 * 16 + warp) * CK + lane * 2) = o2.f2;
    }
}

// ---------------- stage 2a: split-K GEMM (partials only) ----------------
template <int OK, int TM, int ROWS, int CPT, int KS>
__global__ void __launch_bounds__((TM / ROWS) * (OK / CPT)) gemm_kernel(int KD, int wOff) {
    const int KB = 32;
    const int THREADS = (TM / ROWS) * (OK / CPT);
    const int NW4 = (KB * OK / 4 + THREADS - 1) / THREADS;
    const int NF4 = (TM * KB / 4 + THREADS - 1) / THREADS;
    __shared__ __align__(16) float Wt[KB * OK];
    __shared__ __align__(16) float Ft[TM * KB];
    int tid = threadIdx.x;
    int i0 = blockIdx.x * TM;
    int KC = KD / KS;
    int k0 = blockIdx.y * KC;
    int NCH = KC / KB;

    const float* Wsrc = g_Wbig + wOff + (size_t)k0 * OK;

    float4 wreg[NW4], freg[NF4];
    {
        const float4* src = (const float4*)Wsrc;
#pragma unroll
        for (int u = 0; u < NW4; ++u) {
            int x = tid + u * THREADS;
            if (x < KB * OK / 4) wreg[u] = src[x];
        }
#pragma unroll
        for (int u = 0; u < NF4; ++u) {
            int x = tid + u * THREADS;
            if (x < TM * KB / 4) {
                int row = x / (KB / 4), kc = x % (KB / 4);
                freg[u] = *(const float4*)(g_F + (size_t)(i0 + row) * KD + k0 + kc * 4);
            }
        }
    }

    int rg = tid / (OK / CPT);
    int cg = (tid % (OK / CPT)) * CPT;
    unsigned long long accp[ROWS][CPT / 2];
#pragma unroll
    for (int r = 0; r < ROWS; ++r)
#pragma unroll
        for (int c = 0; c < CPT / 2; ++c) accp[r][c] = 0ull;

    for (int ch = 0; ch < NCH; ++ch) {
        __syncthreads();
#pragma unroll
        for (int u = 0; u < NW4; ++u) {
            int x = tid + u * THREADS;
            if (x < KB * OK / 4) ((float4*)Wt)[x] = wreg[u];
        }
#pragma unroll
        for (int u = 0; u < NF4; ++u) {
            int x = tid + u * THREADS;
            if (x < TM * KB / 4) ((float4*)Ft)[x] = freg[u];
        }
        __syncthreads();
        if (ch + 1 < NCH) {
            const float4* src = (const float4*)(Wsrc + (size_t)(ch + 1) * KB * OK);
#pragma unroll
            for (int u = 0; u < NW4; ++u) {
                int x = tid + u * THREADS;
                if (x < KB * OK / 4) wreg[u] = src[x];
            }
#pragma unroll
            for (int u = 0; u < NF4; ++u) {
                int x = tid + u * THREADS;
                if (x < TM * KB / 4) {
                    int rr = x / (KB / 4), kc = x % (KB / 4);
                    freg[u] = *(const float4*)(g_F + (size_t)(i0 + rr) * KD + k0 + (ch + 1) * KB + kc * 4);
                }
            }
        }
#pragma unroll 4
        for (int k = 0; k < KB; ++k) {
            unsigned long long fp[ROWS];
#pragma unroll
            for (int r = 0; r < ROWS; ++r)
                fp[r] = pack2(Ft[(rg * ROWS + r) * KB + k]);
#pragma unroll
            for (int c = 0; c < CPT; c += 4) {
                F4U w;
                w.f4 = *(const float4*)&Wt[k * OK + cg + c];
#pragma unroll
                for (int r = 0; r < ROWS; ++r) {
                    accp[r][c / 2]     = ffma2(fp[r], w.u2[0], accp[r][c / 2]);
                    accp[r][c / 2 + 1] = ffma2(fp[r], w.u2[1], accp[r][c / 2 + 1]);
                }
            }
        }
    }

#pragma unroll
    for (int r = 0; r < ROWS; ++r) {
        float* dst = g_part + ((size_t)blockIdx.y * BN + i0 + rg * ROWS + r) * OK + cg;
#pragma unroll
        for (int c = 0; c < CPT; c += 4) {
            F4U o;
            o.u2[0] = accp[r][c / 2];
            o.u2[1] = accp[r][c / 2 + 1];
            *(float4*)&dst[c] = o.f4;
        }
    }
}

// ---------------- stage 2b: 4-way split-parallel reduce + dense + epilogue ----------------
// 256 threads = 64 outputs/block (4 lanes per output). Octet (8 om) = 1 warp.
template <int OK, int KS, int CK>
__global__ void __launch_bounds__(256) reduce_kernel(int mode, int dOff,
                                                     int ain, int aout) {
    int tid = threadIdx.x;
    int warp = tid >> 5, lane = tid & 31;
    int s = lane & 3;
    int gidx = blockIdx.x * 64 + warp * 8 + (lane >> 2);
    int bi = gidx / OK, om = gidx % OK;

    float oc = 0.f;
#pragma unroll
    for (int ks = s; ks < KS; ks += 4)
        oc += g_part[((size_t)ks * BN + bi) * OK + om];

    const float* __restrict__ densein = (ain == 0) ? g_regD : (ain == 1) ? g_actA : g_actB;
    float* __restrict__ actout = (aout == 1) ? g_actA : g_actB;
    const float* WdT = g_WdT + dOff;
    const float* x = densein + (size_t)bi * CK;
    float od = 0.f;
    const int CPT = CK / 4;
#pragma unroll
    for (int u = 0; u < CPT; ++u) {
        int cn = s * CPT + u;
        od = fmaf(x[cn], WdT[cn * OK + om], od);
    }
    oc += __shfl_xor_sync(0xffffffffu, oc, 1);
    oc += __shfl_xor_sync(0xffffffffu, oc, 2);
    od += __shfl_xor_sync(0xffffffffu, od, 1);
    od += __shfl_xor_sync(0xffffffffu, od, 2);

    if (mode == 0) {
        float sc = oc * oc;
        sc += __shfl_xor_sync(0xffffffffu, sc, 4);
        sc += __shfl_xor_sync(0xffffffffu, sc, 8);
        sc += __shfl_xor_sync(0xffffffffu, sc, 16);
        float mc = sc + 1e-6f;
        float sd = od * od;
        sd += __shfl_xor_sync(0xffffffffu, sd, 4);
        sd += __shfl_xor_sync(0xffffffffu, sd, 8);
        sd += __shfl_xor_sync(0xffffffffu, sd, 16);
        float md = sd + 1e-6f;
        if (s == 0) {
            g_out[bi * 64 + om] = oc;
            g_out[bi * 64 + 32 + om] = od;
            actout[bi * 64 + om] = oc / mc * fmaxf(mc - 0.2f, 0.f);
            actout[bi * 64 + 32 + om] = od / md * fmaxf(md - 0.2f, 0.f);
        }
    } else {
        float v = oc + od;
        if (mode == 2) v += g_out[bi * OK + om];
        float sq = v * v;
        sq += __shfl_xor_sync(0xffffffffu, sq, 4);
        sq += __shfl_xor_sync(0xffffffffu, sq, 8);
        sq += __shfl_xor_sync(0xffffffffu, sq, 16);
        float mg = sq + 1e-6f;
        if (s == 0) {
            g_out[bi * OK + om] = v;
            actout[bi * OK + om] = v / mg * fmaxf(mg - 0.2f, 0.f);
        }
    }
}

// ---------------- last layer: split-parallel reduce + dense + projection ----------------
// Outputs BN*24; one warp = one (bi, ch) octet. KS=8, CK=64.
__global__ void __launch_bounds__(256) reduce_last(const float* __restrict__ p0,
                                                   const float* __restrict__ pc,
                                                   const float* __restrict__ pd,
                                                   float* __restrict__ outp) {
    const int OK = 24, KS = 8, CK = 64;
    int tid = threadIdx.x;
    int warp = tid >> 5, lane = tid & 31;
    int s = lane & 3;
    int gidx = blockIdx.x * 64 + warp * 8 + (lane >> 2);
    int bi = gidx / OK, om = gidx % OK;
    int m = om & 7, ch = om >> 3;

    float oc = 0.f;
#pragma unroll
    for (int ks = s; ks < KS; ks += 4)
        oc += g_part[((size_t)ks * BN + bi) * OK + om];

    const float* WdT = g_WdT + 24576;
    const float* x = g_actB + (size_t)bi * CK;
    float od = 0.f;
#pragma unroll
    for (int u = 0; u < 16; ++u) {
        int cn = s * 16 + u;
        od = fmaf(x[cn], WdT[cn * OK + om], od);
    }
    oc += __shfl_xor_sync(0xffffffffu, oc, 1);
    oc += __shfl_xor_sync(0xffffffffu, oc, 2);
    od += __shfl_xor_sync(0xffffffffu, od, 1);
    od += __shfl_xor_sync(0xffffffffu, od, 2);

    float th = (float)m * 0.78539816339744831f;
    float cs = cosf(th), sn = sinf(th);
    float c0 = pc[0], c1 = pc[1], d0 = pd[0], d1 = pd[1];
    float resx = oc * (c0 * cs - c1 * sn) + od * (d0 * cs - d1 * sn);
    float resy = oc * (c0 * sn + c1 * cs) + od * (d0 * sn + d1 * cs);
    resx += __shfl_xor_sync(0xffffffffu, resx, 4);
    resx += __shfl_xor_sync(0xffffffffu, resx, 8);
    resx += __shfl_xor_sync(0xffffffffu, resx, 16);
    resy += __shfl_xor_sync(0xffffffffu, resy, 4);
    resy += __shfl_xor_sync(0xffffffffu, resy, 8);
    resy += __shfl_xor_sync(0xffffffffu, resy, 16);

    if (lane == 0) {
        const float CORR = 1.0f / 128.0f;
        resx *= CORR;
        resy *= CORR;
        if (ch == 0) {
            float px = g_p1[bi * 2 + 0] + resx;
            float py = g_p1[bi * 2 + 1] + resy;
            outp[bi * 2 + 0] = px;
            outp[bi * 2 + 1] = py;
            outp[BN * 2 + bi * 2 + 0] = px - p0[bi * 2 + 0];
            outp[BN * 2 + bi * 2 + 1] = py - p0[bi * 2 + 1];
        } else {
            outp[BN * 4 + bi * 4 + (ch - 1) * 2 + 0] = resx;
            outp[BN * 4 + bi * 4 + (ch - 1) * 2 + 1] = resy;
        }
    }
}

// ---------------- launch ----------------
extern "C" void kernel_launch(void* const* d_in, const int* in_sizes, int n_in,
                              void* d_out, int out_size) {
    const float* p0_enc  = (const float*)d_in[0];
    const float* v0_enc  = (const float*)d_in[1];
    const float* p0      = (const float*)d_in[2];
    const float* v0      = (const float*)d_in[3];
    const float* a       = (const float*)d_in[4];
    const float* mask    = (const float*)d_in[5];
    const float* lift_c0 = (const float*)d_in[6];
    const float* Wc0     = (const float*)d_in[7];
    const float* lift_d0 = (const float*)d_in[8];
    const float* Wd0     = (const float*)d_in[9];
    const float* Wc1     = (const float*)d_in[10];
    const float* Wd1     = (const float*)d_in[11];
    const float* Wc2     = (const float*)d_in[12];
    const float* Wd2     = (const float*)d_in[13];
    const float* Wc3     = (const float*)d_in[14];
    const float* Wd3     = (const float*)d_in[15];
    const float* Wc4     = (const float*)d_in[16];
    const float* proj_c4 = (const float*)d_in[17];
    const float* Wd4     = (const float*)d_in[18];
    const float* proj_d4 = (const float*)d_in[19];

    const int NEXP = (1253376 + 26112 + 255) / 256;
    prep_kernel<<<BN + NEXP, 256>>>(mask, p0, v0, a, p0_enc, v0_enc,
                                    lift_c0, lift_d0,
                                    Wc0, Wc1, Wc2, Wc3, Wc4,
                                    Wd0, Wd1, Wd2, Wd3, Wd4);

    const int wOff[5] = {0, 196608, 393216, 786432, 1179648};
    const int dOff[5] = {0, 4096, 8192, 16384, 24576};

    // act ping-pong: L0 -> A; L1: A->B; L2: B->A; L3: A->B; L4: reads B
    // L0: CK=128, OK=32, KD=6144
    stage1_kernel<128><<<BN, 512>>>(0);
    gemm_kernel<32, 128, 2, 8, 16><<<dim3(8, 16), 256>>>(6144, wOff[0]);
    reduce_kernel<32, 16, 128><<<BN * 32 / 64, 256>>>(0, dOff[0], 0, 1);
    // L1: CK=64, OK=64, KD=3072, residual
    stage1_kernel<64><<<BN, 512>>>(1);
    gemm_kernel<64, 64, 2, 8, 16><<<dim3(16, 16), 256>>>(3072, wOff[1]);
    reduce_kernel<64, 16, 64><<<BN * 64 / 64, 256>>>(2, dOff[1], 1, 2);
    // L2: CK=64, OK=128, KD=3072
    stage1_kernel<64><<<BN, 512>>>(2);
    gemm_kernel<128, 32, 2, 8, 8><<<dim3(32, 8), 256>>>(3072, wOff[2]);
    reduce_kernel<128, 8, 64><<<BN * 128 / 64, 256>>>(1, dOff[2], 2, 1);
    // L3: CK=128, OK=64, KD=6144
    stage1_kernel<128><<<BN, 512>>>(1);
    gemm_kernel<64, 64, 2, 8, 16><<<dim3(16, 16), 256>>>(6144, wOff[3]);
    reduce_kernel<64, 16, 128><<<BN * 64 / 64, 256>>>(1, dOff[3], 1, 2);
    // L4: CK=64, OK=24, KD=3072, last (fused projection)
    stage1_kernel<64><<<BN, 512>>>(2);
    gemm_kernel<24, 128, 2, 8, 8><<<dim3(8, 8), 192>>>(3072, wOff[4]);
    reduce_last<<<BN * 24 / 64, 256>>>(p0, proj_c4, proj_d4, (float*)d_out);
}